// round 7
// baseline (speedup 1.0000x reference)
#include <cuda_runtime.h>
#include <cuda_bf16.h>
#include <cstdint>
#include <math.h>

// Problem constants
#define BB 32
#define TT 32
#define KK 196
#define HH 512
#define AA 512
#define GK 512

#define ROWS_ATT (BB * KK)          // 6272
#define ROWS_HID (BB * TT)          // 1024
#define ROWS_ALL (ROWS_ATT + 2 * ROWS_HID)   // 8320

// ---------------------------------------------------------------------------
// Scratch (__device__ globals; no cudaMalloc allowed)
__device__ float g_cg[BB * TT * AA];                 // 2 MB
__device__ float g_cs[BB * TT * AA];                 // 2 MB
__device__ __nv_bfloat16 g_xh[ROWS_ALL * HH];        // concat activations hi
__device__ __nv_bfloat16 g_xl[ROWS_ALL * HH];        // concat activations lo
__device__ __nv_bfloat16 g_wh[3 * AA * HH];          // W^T hi (Wv, Wg, Ws)
__device__ __nv_bfloat16 g_wl[3 * AA * HH];          // W^T lo

// ---------------------------------------------------------------------------
__device__ __forceinline__ float tanh_mufu(float x) {
    float y;
    asm("tanh.approx.f32 %0, %1;" : "=f"(y) : "f"(x));
    return y;
}
__device__ __forceinline__ float warp_sum(float v) {
    #pragma unroll
    for (int o = 16; o; o >>= 1) v += __shfl_xor_sync(0xffffffffu, v, o);
    return v;
}

// mma.sync m16n8k16 row.col f32.bf16.bf16.f32, D == C
__device__ __forceinline__ void hmma(float* c, const uint32_t* a, const uint32_t* b) {
    asm volatile(
        "mma.sync.aligned.m16n8k16.row.col.f32.bf16.bf16.f32 "
        "{%0,%1,%2,%3}, {%4,%5,%6,%7}, {%8,%9}, {%0,%1,%2,%3};"
        : "+f"(c[0]), "+f"(c[1]), "+f"(c[2]), "+f"(c[3])
        : "r"(a[0]), "r"(a[1]), "r"(a[2]), "r"(a[3]), "r"(b[0]), "r"(b[1]));
}

__device__ __forceinline__ uint32_t smem_u32(const void* p) {
    uint32_t a;
    asm("{ .reg .u64 t; cvta.to.shared.u64 t, %1; cvt.u32.u64 %0, t; }" : "=r"(a) : "l"(p));
    return a;
}
__device__ __forceinline__ void cp16(uint32_t dst, const void* src) {
    asm volatile("cp.async.cg.shared.global [%0], [%1], 16;" :: "r"(dst), "l"(src));
}
#define CP_COMMIT() asm volatile("cp.async.commit_group;" ::: "memory")
#define CP_WAIT1()  asm volatile("cp.async.wait_group 1;" ::: "memory")
#define CP_WAIT0()  asm volatile("cp.async.wait_group 0;" ::: "memory")

// ---------------------------------------------------------------------------
// prep: activation hi/lo split (blocks [0, NSPLIT)) + weight transpose/split.
#define NSPLIT ((ROWS_ALL * HH / 4 + 255) / 256)   // 4160

__global__ void prep_kernel(const float* __restrict__ att, const float* __restrict__ hid,
                            const float* __restrict__ sent,
                            const float* __restrict__ Wv, const float* __restrict__ Wg,
                            const float* __restrict__ Ws) {
    int tid = threadIdx.x;
    if (blockIdx.x < NSPLIT) {
        const int N4 = ROWS_ALL * HH / 4;
        int i = blockIdx.x * 256 + tid;
        if (i >= N4) return;
        const float4* src;
        int li;
        if (i < ROWS_ATT * 128)                   { src = (const float4*)att;  li = i; }
        else if (i < (ROWS_ATT + ROWS_HID) * 128) { src = (const float4*)hid;  li = i - ROWS_ATT * 128; }
        else                                      { src = (const float4*)sent; li = i - (ROWS_ATT + ROWS_HID) * 128; }
        float4 v = src[li];
        __nv_bfloat16 h0 = __float2bfloat16(v.x);
        __nv_bfloat16 h1 = __float2bfloat16(v.y);
        __nv_bfloat16 h2 = __float2bfloat16(v.z);
        __nv_bfloat16 h3 = __float2bfloat16(v.w);
        ((__nv_bfloat162*)g_xh)[2 * i]     = __nv_bfloat162(h0, h1);
        ((__nv_bfloat162*)g_xh)[2 * i + 1] = __nv_bfloat162(h2, h3);
        ((__nv_bfloat162*)g_xl)[2 * i]     = __nv_bfloat162(__float2bfloat16(v.x - __bfloat162float(h0)),
                                                            __float2bfloat16(v.y - __bfloat162float(h1)));
        ((__nv_bfloat162*)g_xl)[2 * i + 1] = __nv_bfloat162(__float2bfloat16(v.z - __bfloat162float(h2)),
                                                            __float2bfloat16(v.w - __bfloat162float(h3)));
    } else {
        __shared__ float t[32][33];
        int zb = blockIdx.x - NSPLIT;
        int z = zb >> 8, rem = zb & 255;
        const float* W = (z == 0) ? Wv : (z == 1) ? Wg : Ws;
        size_t wo = (size_t)z * AA * HH;
        int a0 = (rem & 15) * 32, h0 = (rem >> 4) * 32;
        int tx = tid & 31, ty = tid >> 5;
        #pragma unroll
        for (int r = ty; r < 32; r += 8)
            t[r][tx] = W[(size_t)(h0 + r) * AA + a0 + tx];
        __syncthreads();
        #pragma unroll
        for (int r = ty; r < 32; r += 8) {
            float v = t[tx][r];
            __nv_bfloat16 hh = __float2bfloat16(v);
            g_wh[wo + (size_t)(a0 + r) * HH + h0 + tx] = hh;
            g_wl[wo + (size_t)(a0 + r) * HH + h0 + tx] = __float2bfloat16(v - __bfloat162float(hh));
        }
    }
}

// ---------------------------------------------------------------------------
// cg/cs GEMM (R5-proven structure), grid (4, 16), 256 thr, block 128x128.
#define SROW 40
#define TILE_E (128 * SROW)
#define TILE_B (TILE_E * 2)
#define GS_DSMEM (TILE_B * 4 * 2)       // 81920

__global__ void __launch_bounds__(256) mma_gemm_gs(float* __restrict__ cg,
                                                   float* __restrict__ cs) {
    extern __shared__ __nv_bfloat16 dynsm[];
    uint32_t sb = smem_u32(dynsm);
    const __nv_bfloat16* Xh = g_xh;
    const __nv_bfloat16* Xl = g_xl;

    int tid = threadIdx.x, wid = tid >> 5, lane = tid & 31;
    int wm = wid >> 2, wn = wid & 3;
    int g = lane >> 2, tig = lane & 3;
    int my = blockIdx.y;
    int n0 = blockIdx.x * 128;

    int arow0; size_t wo; float* C; int crow0;
    if (my < 8) { arow0 = ROWS_ATT + my * 128;            wo = (size_t)AA * HH;     C = cg; crow0 = my * 128; }
    else        { arow0 = ROWS_ATT + ROWS_HID + (my - 8) * 128; wo = 2 * (size_t)AA * HH; C = cs; crow0 = (my - 8) * 128; }

    float acc[4][4][4];
    #pragma unroll
    for (int i = 0; i < 4; i++)
        #pragma unroll
        for (int j = 0; j < 4; j++)
            #pragma unroll
            for (int q = 0; q < 4; q++) acc[i][j][q] = 0.0f;

    int lr = tid >> 2, lc = (tid & 3) * 8;

    auto load_stage = [&](int s, int k0) {
        uint32_t base = sb + (uint32_t)(s * 4) * TILE_B;
        #pragma unroll
        for (int p = 0; p < 2; p++) {
            int r = lr + 64 * p;
            uint32_t soff = (uint32_t)(r * SROW + lc) * 2;
            cp16(base + 0 * TILE_B + soff, Xh + (size_t)(arow0 + r) * GK + k0 + lc);
            cp16(base + 1 * TILE_B + soff, Xl + (size_t)(arow0 + r) * GK + k0 + lc);
            cp16(base + 2 * TILE_B + soff, g_wh + wo + (size_t)(n0 + r) * HH + k0 + lc);
            cp16(base + 3 * TILE_B + soff, g_wl + wo + (size_t)(n0 + r) * HH + k0 + lc);
        }
    };

    load_stage(0, 0);
    CP_COMMIT();

    const int NIT = GK / 32;
    for (int it = 0; it < NIT; it++) {
        if (it + 1 < NIT) { load_stage((it + 1) & 1, (it + 1) * 32); CP_COMMIT(); CP_WAIT1(); }
        else              { CP_WAIT0(); }
        __syncthreads();

        const __nv_bfloat16* sAh = dynsm + (size_t)((it & 1) * 4 + 0) * TILE_E;
        const __nv_bfloat16* sAl = dynsm + (size_t)((it & 1) * 4 + 1) * TILE_E;
        const __nv_bfloat16* sBh = dynsm + (size_t)((it & 1) * 4 + 2) * TILE_E;
        const __nv_bfloat16* sBl = dynsm + (size_t)((it & 1) * 4 + 3) * TILE_E;

        #pragma unroll
        for (int ks = 0; ks < 2; ks++) {
            int c0 = ks * 16 + 2 * tig;
            uint32_t aH[4][4], aL[4][4], bH[4][2], bL[4][2];
            #pragma unroll
            for (int mf = 0; mf < 4; mf++) {
                int mr = wm * 64 + mf * 16;
                aH[mf][0] = *(const uint32_t*)&sAh[(mr + g) * SROW + c0];
                aH[mf][1] = *(const uint32_t*)&sAh[(mr + g + 8) * SROW + c0];
                aH[mf][2] = *(const uint32_t*)&sAh[(mr + g) * SROW + c0 + 8];
                aH[mf][3] = *(const uint32_t*)&sAh[(mr + g + 8) * SROW + c0 + 8];
                aL[mf][0] = *(const uint32_t*)&sAl[(mr + g) * SROW + c0];
                aL[mf][1] = *(const uint32_t*)&sAl[(mr + g + 8) * SROW + c0];
                aL[mf][2] = *(const uint32_t*)&sAl[(mr + g) * SROW + c0 + 8];
                aL[mf][3] = *(const uint32_t*)&sAl[(mr + g + 8) * SROW + c0 + 8];
            }
            #pragma unroll
            for (int nf = 0; nf < 4; nf++) {
                int nr = wn * 32 + nf * 8;
                bH[nf][0] = *(const uint32_t*)&sBh[(nr + g) * SROW + c0];
                bH[nf][1] = *(const uint32_t*)&sBh[(nr + g) * SROW + c0 + 8];
                bL[nf][0] = *(const uint32_t*)&sBl[(nr + g) * SROW + c0];
                bL[nf][1] = *(const uint32_t*)&sBl[(nr + g) * SROW + c0 + 8];
            }
            #pragma unroll
            for (int mf = 0; mf < 4; mf++)
                #pragma unroll
                for (int nf = 0; nf < 4; nf++) hmma(acc[mf][nf], aH[mf], bH[nf]);
            #pragma unroll
            for (int mf = 0; mf < 4; mf++)
                #pragma unroll
                for (int nf = 0; nf < 4; nf++) hmma(acc[mf][nf], aH[mf], bL[nf]);
            #pragma unroll
            for (int mf = 0; mf < 4; mf++)
                #pragma unroll
                for (int nf = 0; nf < 4; nf++) hmma(acc[mf][nf], aL[mf], bH[nf]);
        }
        __syncthreads();
    }

    #pragma unroll
    for (int mf = 0; mf < 4; mf++) {
        int row = crow0 + wm * 64 + mf * 16 + g;
        #pragma unroll
        for (int nf = 0; nf < 4; nf++) {
            int col = n0 + wn * 32 + nf * 8 + 2 * tig;
            *(float2*)&C[(size_t)row * AA + col] = make_float2(acc[mf][nf][0], acc[mf][nf][1]);
            *(float2*)&C[(size_t)(row + 8) * AA + col] = make_float2(acc[mf][nf][2], acc[mf][nf][3]);
        }
    }
}

// ---------------------------------------------------------------------------
// FUSED cv-GEMM + z epilogue.
// grid (4 a-tiles, 98 m-tiles), 128 threads (4 warps). Block tile 64(m) x 128(a).
// Warp wn handles a-cols [wn*32, wn*32+32), all 64 m rows (wm == 0 layout).
// Mainloop: bf16x3 cp.async pipeline (K=512, chunk 32, 2 stages).
// Epilogue: acc holds COMPLETE cv for (m-row, a-col); compute
//   z[b,t,k] += sum_a wh[a] * tanh(cv + cg[b,t,a])  via quad shfl + atomicAdd.
// smem (elements of bf16): stage s: Ah@s*15360 (2560), Al(+2560), Bh(+5120,5120),
//   Bl(+10240); after 30720: cg slabs (2 x 32 x 128 fp32).
#define FA_TILE_E 2560                 // 64*40
#define FB_TILE_E 5120                 // 128*40
#define FSTAGE_E  15360                // elements per stage
#define FSTAGE_B  30720                // bytes per stage
#define CVZ_DSMEM (2 * FSTAGE_B + 2 * 32 * 128 * 4)   // 61440 + 32768 = 94208

__global__ void __launch_bounds__(128) cvz_fused(const float* __restrict__ wh,
                                                 float* __restrict__ z) {
    extern __shared__ __nv_bfloat16 dynsm[];
    uint32_t sb = smem_u32(dynsm);
    float* s_cg = (float*)(dynsm + 2 * FSTAGE_E);

    int tid = threadIdx.x, wn = tid >> 5, lane = tid & 31;
    int g = lane >> 2, tig = lane & 3;
    int n0 = blockIdx.x * 128;
    int m0 = blockIdx.y * 64;          // global (b,k) row base, < 6272

    float acc[4][4][4];
    #pragma unroll
    for (int i = 0; i < 4; i++)
        #pragma unroll
        for (int j = 0; j < 4; j++)
            #pragma unroll
            for (int q = 0; q < 4; q++) acc[i][j][q] = 0.0f;

    int lr = tid >> 2, lc = (tid & 3) * 8;   // lr 0..31, lc 0/8/16/24

    auto load_stage = [&](int s, int k0) {
        uint32_t base = sb + (uint32_t)s * FSTAGE_B;
        #pragma unroll
        for (int p = 0; p < 2; p++) {        // A: 64 rows
            int r = lr + 32 * p;
            uint32_t soff = (uint32_t)(r * SROW + lc) * 2;
            cp16(base + soff,        g_xh + (size_t)(m0 + r) * GK + k0 + lc);
            cp16(base + 5120 + soff, g_xl + (size_t)(m0 + r) * GK + k0 + lc);
        }
        #pragma unroll
        for (int p = 0; p < 4; p++) {        // B: 128 rows (Wv: wo = 0)
            int r = lr + 32 * p;
            uint32_t soff = (uint32_t)(r * SROW + lc) * 2;
            cp16(base + 10240 + soff, g_wh + (size_t)(n0 + r) * HH + k0 + lc);
            cp16(base + 20480 + soff, g_wl + (size_t)(n0 + r) * HH + k0 + lc);
        }
    };

    load_stage(0, 0);
    CP_COMMIT();

    const int NIT = GK / 32;
    for (int it = 0; it < NIT; it++) {
        if (it + 1 < NIT) { load_stage((it + 1) & 1, (it + 1) * 32); CP_COMMIT(); CP_WAIT1(); }
        else              { CP_WAIT0(); }
        __syncthreads();

        const __nv_bfloat16* sAh = dynsm + (size_t)(it & 1) * FSTAGE_E;
        const __nv_bfloat16* sAl = sAh + FA_TILE_E;
        const __nv_bfloat16* sBh = sAh + 2 * FA_TILE_E;
        const __nv_bfloat16* sBl = sBh + FB_TILE_E;

        #pragma unroll
        for (int ks = 0; ks < 2; ks++) {
            int c0 = ks * 16 + 2 * tig;
            uint32_t aH[4][4], aL[4][4], bH[4][2], bL[4][2];
            #pragma unroll
            for (int mf = 0; mf < 4; mf++) {
                int mr = mf * 16;
                aH[mf][0] = *(const uint32_t*)&sAh[(mr + g) * SROW + c0];
                aH[mf][1] = *(const uint32_t*)&sAh[(mr + g + 8) * SROW + c0];
                aH[mf][2] = *(const uint32_t*)&sAh[(mr + g) * SROW + c0 + 8];
                aH[mf][3] = *(const uint32_t*)&sAh[(mr + g + 8) * SROW + c0 + 8];
                aL[mf][0] = *(const uint32_t*)&sAl[(mr + g) * SROW + c0];
                aL[mf][1] = *(const uint32_t*)&sAl[(mr + g + 8) * SROW + c0];
                aL[mf][2] = *(const uint32_t*)&sAl[(mr + g) * SROW + c0 + 8];
                aL[mf][3] = *(const uint32_t*)&sAl[(mr + g + 8) * SROW + c0 + 8];
            }
            #pragma unroll
            for (int nf = 0; nf < 4; nf++) {
                int nr = wn * 32 + nf * 8;
                bH[nf][0] = *(const uint32_t*)&sBh[(nr + g) * SROW + c0];
                bH[nf][1] = *(const uint32_t*)&sBh[(nr + g) * SROW + c0 + 8];
                bL[nf][0] = *(const uint32_t*)&sBl[(nr + g) * SROW + c0];
                bL[nf][1] = *(const uint32_t*)&sBl[(nr + g) * SROW + c0 + 8];
            }
            #pragma unroll
            for (int mf = 0; mf < 4; mf++)
                #pragma unroll
                for (int nf = 0; nf < 4; nf++) hmma(acc[mf][nf], aH[mf], bH[nf]);
            #pragma unroll
            for (int mf = 0; mf < 4; mf++)
                #pragma unroll
                for (int nf = 0; nf < 4; nf++) hmma(acc[mf][nf], aH[mf], bL[nf]);
            #pragma unroll
            for (int mf = 0; mf < 4; mf++)
                #pragma unroll
                for (int nf = 0; nf < 4; nf++) hmma(acc[mf][nf], aL[mf], bH[nf]);
        }
        __syncthreads();
    }

    // ---- z epilogue ----
    int b0 = m0 / KK;
    int b1 = (m0 + 63) / KK;
    int nslab = (b1 != b0) ? 2 : 1;

    // load cg slab(s): [t 0..31][a n0..n0+127] fp32
    for (int l = 0; l < nslab; l++) {
        int b = (l == 0) ? b0 : b1;
        for (int i = tid * 4; i < 32 * 128; i += 128 * 4) {
            int t = i >> 7, ca = i & 127;
            *(float4*)&s_cg[l * 4096 + i] =
                *(const float4*)&g_cg[((size_t)(b * TT + t)) * AA + n0 + ca];
        }
    }
    __syncthreads();

    // per-thread row metadata: rows = m0 + mf*16 + g + half*8
    int bl[4][2], bt[4][2], kr[4][2];
    #pragma unroll
    for (int mf = 0; mf < 4; mf++)
        #pragma unroll
        for (int h = 0; h < 2; h++) {
            int rowg = m0 + mf * 16 + g + h * 8;
            int bb = rowg / KK;
            bl[mf][h] = bb - b0;
            bt[mf][h] = bb * TT;
            kr[mf][h] = rowg - bb * KK;
        }

    float2 wh2[4];
    #pragma unroll
    for (int nf = 0; nf < 4; nf++)
        wh2[nf] = *(const float2*)&wh[n0 + wn * 32 + nf * 8 + 2 * tig];

    for (int t = 0; t < 32; t++) {
        float2 cgv[2][4];
        #pragma unroll
        for (int nf = 0; nf < 4; nf++)
            cgv[0][nf] = *(const float2*)&s_cg[(size_t)t * 128 + wn * 32 + nf * 8 + 2 * tig];
        if (nslab == 2) {
            #pragma unroll
            for (int nf = 0; nf < 4; nf++)
                cgv[1][nf] = *(const float2*)&s_cg[4096 + (size_t)t * 128 + wn * 32 + nf * 8 + 2 * tig];
        }

        float p[4][2];
        #pragma unroll
        for (int mf = 0; mf < 4; mf++)
            #pragma unroll
            for (int h = 0; h < 2; h++) {
                int l = bl[mf][h];
                float s0 = 0.0f, s1 = 0.0f;
                #pragma unroll
                for (int nf = 0; nf < 4; nf++) {
                    float x = acc[mf][nf][h * 2 + 0] + cgv[l][nf].x;
                    float y = acc[mf][nf][h * 2 + 1] + cgv[l][nf].y;
                    s0 = fmaf(wh2[nf].x, tanh_mufu(x), s0);
                    s1 = fmaf(wh2[nf].y, tanh_mufu(y), s1);
                }
                p[mf][h] = s0 + s1;
            }

        // reduce over the 4 tig lanes (same rows, different cols)
        #pragma unroll
        for (int mf = 0; mf < 4; mf++)
            #pragma unroll
            for (int h = 0; h < 2; h++) {
                float v = p[mf][h];
                v += __shfl_xor_sync(0xffffffffu, v, 1);
                v += __shfl_xor_sync(0xffffffffu, v, 2);
                p[mf][h] = v;
            }
        if (tig == 0) {
            #pragma unroll
            for (int mf = 0; mf < 4; mf++)
                #pragma unroll
                for (int h = 0; h < 2; h++)
                    atomicAdd(&z[(size_t)(bt[mf][h] + t) * KK + kr[mf][h]], p[mf][h]);
        }
    }
}

// ---------------------------------------------------------------------------
// Softmax over K=196 + beta (+ inline z_ext); one warp per (b,t) row
__global__ void softmax_kernel(float* __restrict__ zp, float* __restrict__ beta,
                               const float* __restrict__ wh) {
    const float L2E = 1.4426950408889634f;
    int wid = threadIdx.x >> 5, lane = threadIdx.x & 31;
    int row = blockIdx.x * 8 + wid;
    float* zr = zp + (size_t)row * KK;

    // z_ext = sum_a wh[a]*tanh(cs+cg), float4 per lane
    float ze;
    {
        const float* cs = g_cs + (size_t)row * AA;
        const float* cg = g_cg + (size_t)row * AA;
        float a0 = 0.0f;
        #pragma unroll
        for (int j = 0; j < 4; j++) {
            int i4 = (j * 32 + lane) * 4;
            float4 c1 = *(const float4*)&cs[i4];
            float4 c2 = *(const float4*)&cg[i4];
            float4 w4 = *(const float4*)&wh[i4];
            a0 = fmaf(w4.x, tanh_mufu(c1.x + c2.x), a0);
            a0 = fmaf(w4.y, tanh_mufu(c1.y + c2.y), a0);
            a0 = fmaf(w4.z, tanh_mufu(c1.z + c2.z), a0);
            a0 = fmaf(w4.w, tanh_mufu(c1.w + c2.w), a0);
        }
        ze = warp_sum(a0);
    }

    float v[7];
    float m = -INFINITY;
    #pragma unroll
    for (int j = 0; j < 7; j++) {
        int k = lane + 32 * j;
        v[j] = (k < KK) ? zr[k] : -INFINITY;
        m = fmaxf(m, v[j]);
    }
    #pragma unroll
    for (int o = 16; o; o >>= 1) m = fmaxf(m, __shfl_xor_sync(0xffffffffu, m, o));

    float s = 0.0f;
    #pragma unroll
    for (int j = 0; j < 7; j++) {
        float e = exp2f((v[j] - m) * L2E);
        v[j] = e;
        s += e;
    }
    s = warp_sum(s);

    float inv = __fdividef(1.0f, s);
    #pragma unroll
    for (int j = 0; j < 7; j++) {
        int k = lane + 32 * j;
        if (k < KK) zr[k] = v[j] * inv;
    }

    if (lane == 0) {
        float m2 = fmaxf(m, ze);
        float ee = exp2f((ze - m2) * L2E);
        float s2 = s * exp2f((m - m2) * L2E) + ee;
        beta[row] = __fdividef(ee, s2);
    }
}

// ---------------------------------------------------------------------------
// c_hat[b,t,:] = beta*sentinel + (1-beta) * sum_k alpha[b,t,k]*att_feats[b,k,:]
__global__ void ct_kernel(const float* __restrict__ af, const float* __restrict__ sent,
                          const float* __restrict__ alpha, const float* __restrict__ beta,
                          float* __restrict__ chat) {
    __shared__ float s_alpha[8][KK];
    __shared__ float s_beta[8];
    int b = blockIdx.x, tg = blockIdx.y;
    int tid = threadIdx.x;
    int trow0 = b * TT + tg * 8;

    for (int i = tid; i < 8 * KK; i += 256)
        s_alpha[i / KK][i % KK] = alpha[(size_t)(trow0 + i / KK) * KK + i % KK];
    if (tid < 8) s_beta[tid] = beta[trow0 + tid];
    __syncthreads();

    float acc[8][2];
    #pragma unroll
    for (int t = 0; t < 8; t++) { acc[t][0] = 0.0f; acc[t][1] = 0.0f; }

    const float* afb = af + (size_t)b * KK * HH;
    int h2 = tid * 2;
    for (int k = 0; k < KK; k++) {
        float2 vv = *(const float2*)(afb + (size_t)k * HH + h2);
        #pragma unroll
        for (int t = 0; t < 8; t++) {
            float al = s_alpha[t][k];
            acc[t][0] = fmaf(al, vv.x, acc[t][0]);
            acc[t][1] = fmaf(al, vv.y, acc[t][1]);
        }
    }

    #pragma unroll
    for (int t = 0; t < 8; t++) {
        float be = s_beta[t];
        float om = 1.0f - be;
        size_t row = (size_t)(trow0 + t);
        float2 sv = *(const float2*)(sent + row * HH + h2);
        float2 o;
        o.x = be * sv.x + om * acc[t][0];
        o.y = be * sv.y + om * acc[t][1];
        *(float2*)(chat + row * HH + h2) = o;
    }
}

// ---------------------------------------------------------------------------
extern "C" void kernel_launch(void* const* d_in, const int* in_sizes, int n_in,
                              void* d_out, int out_size) {
    const float* att  = (const float*)d_in[0];
    const float* hid  = (const float*)d_in[1];
    const float* sent = (const float*)d_in[2];
    const float* Wv   = (const float*)d_in[3];
    const float* Wg   = (const float*)d_in[4];
    const float* Ws   = (const float*)d_in[5];
    const float* wh   = (const float*)d_in[6];

    float* out   = (float*)d_out;
    float* chat  = out;                               // 524288
    float* alpha = out + (size_t)BB * TT * HH;        // 200704 (z accumulates here)
    float* beta  = alpha + (size_t)BB * TT * KK;      // 1024

    float *cg, *cs;
    cudaGetSymbolAddress((void**)&cg, g_cg);
    cudaGetSymbolAddress((void**)&cs, g_cs);
    cudaFuncSetAttribute(mma_gemm_gs, cudaFuncAttributeMaxDynamicSharedMemorySize, GS_DSMEM);
    cudaFuncSetAttribute(cvz_fused,   cudaFuncAttributeMaxDynamicSharedMemorySize, CVZ_DSMEM);

    // 1. prep: activation split + weight transpose/split
    prep_kernel<<<NSPLIT + 768, 256>>>(att, hid, sent, Wv, Wg, Ws);
    // 2. zero z accumulator (atomics add into it)
    cudaMemsetAsync(alpha, 0, (size_t)BB * TT * KK * sizeof(float));
    // 3. cg & cs GEMMs
    mma_gemm_gs<<<dim3(4, 16), 256, GS_DSMEM>>>(cg, cs);
    // 4. fused cv GEMM + tanh-reduction into z
    cvz_fused<<<dim3(4, 98), 128, CVZ_DSMEM>>>(wh, alpha);
    // 5. softmax + beta (+ inline z_ext)
    softmax_kernel<<<128, 256>>>(alpha, beta, wh);
    // 6. c_t + sentinel blend
    ct_kernel<<<dim3(32, 4), 256>>>(att, sent, alpha, beta, chat);
}

// round 8
// speedup vs baseline: 1.0812x; 1.0812x over previous
#include <cuda_runtime.h>
#include <cuda_bf16.h>
#include <cstdint>
#include <math.h>

// Problem constants
#define BB 32
#define TT 32
#define KK 196
#define HH 512
#define AA 512
#define GK 512

#define ROWS_ATT (BB * KK)          // 6272
#define ROWS_HID (BB * TT)          // 1024
#define ROWS_ALL (ROWS_ATT + 2 * ROWS_HID)   // 8320

// ---------------------------------------------------------------------------
// Scratch (__device__ globals; no cudaMalloc allowed)
__device__ float g_cv[BB * KK * AA];                 // 12.8 MB
__device__ float g_cg[BB * TT * AA];                 // 2 MB
__device__ float g_cs[BB * TT * AA];                 // 2 MB
__device__ float g_zext[BB * TT];
__device__ __nv_bfloat16 g_xh[ROWS_ALL * HH];        // concat activations hi
__device__ __nv_bfloat16 g_xl[ROWS_ALL * HH];        // concat activations lo
__device__ __nv_bfloat16 g_wh[3 * AA * HH];          // W^T hi (Wv, Wg, Ws)
__device__ __nv_bfloat16 g_wl[3 * AA * HH];          // W^T lo

// ---------------------------------------------------------------------------
__device__ __forceinline__ float tanh_mufu(float x) {
    float y;
    asm("tanh.approx.f32 %0, %1;" : "=f"(y) : "f"(x));
    return y;
}
__device__ __forceinline__ float warp_sum(float v) {
    #pragma unroll
    for (int o = 16; o; o >>= 1) v += __shfl_xor_sync(0xffffffffu, v, o);
    return v;
}

// mma.sync m16n8k16 row.col f32.bf16.bf16.f32, D == C
__device__ __forceinline__ void hmma(float* c, const uint32_t* a, const uint32_t* b) {
    asm volatile(
        "mma.sync.aligned.m16n8k16.row.col.f32.bf16.bf16.f32 "
        "{%0,%1,%2,%3}, {%4,%5,%6,%7}, {%8,%9}, {%0,%1,%2,%3};"
        : "+f"(c[0]), "+f"(c[1]), "+f"(c[2]), "+f"(c[3])
        : "r"(a[0]), "r"(a[1]), "r"(a[2]), "r"(a[3]), "r"(b[0]), "r"(b[1]));
}

#define LDSM4(r0, r1, r2, r3, addr) \
    asm volatile("ldmatrix.sync.aligned.m8n8.x4.shared.b16 {%0,%1,%2,%3}, [%4];" \
                 : "=r"(r0), "=r"(r1), "=r"(r2), "=r"(r3) : "r"(addr))

__device__ __forceinline__ uint32_t smem_u32(const void* p) {
    uint32_t a;
    asm("{ .reg .u64 t; cvta.to.shared.u64 t, %1; cvt.u32.u64 %0, t; }" : "=r"(a) : "l"(p));
    return a;
}
__device__ __forceinline__ void cp16(uint32_t dst, const void* src) {
    asm volatile("cp.async.cg.shared.global [%0], [%1], 16;" :: "r"(dst), "l"(src));
}
#define CP_COMMIT() asm volatile("cp.async.commit_group;" ::: "memory")
#define CP_WAIT1()  asm volatile("cp.async.wait_group 1;" ::: "memory")
#define CP_WAIT0()  asm volatile("cp.async.wait_group 0;" ::: "memory")

// ---------------------------------------------------------------------------
// fp32 -> bf16 hi/lo split; all three activations in one launch.
__global__ void split_all(const float* __restrict__ att, const float* __restrict__ hid,
                          const float* __restrict__ sent,
                          __nv_bfloat16* __restrict__ H, __nv_bfloat16* __restrict__ L) {
    const int N4 = ROWS_ALL * HH / 4;
    int i = blockIdx.x * blockDim.x + threadIdx.x;
    if (i >= N4) return;
    const float4* src;
    int li;
    if (i < ROWS_ATT * 128)            { src = (const float4*)att;  li = i; }
    else if (i < (ROWS_ATT + ROWS_HID) * 128) { src = (const float4*)hid;  li = i - ROWS_ATT * 128; }
    else                               { src = (const float4*)sent; li = i - (ROWS_ATT + ROWS_HID) * 128; }
    float4 v = src[li];
    __nv_bfloat16 h0 = __float2bfloat16(v.x);
    __nv_bfloat16 h1 = __float2bfloat16(v.y);
    __nv_bfloat16 h2 = __float2bfloat16(v.z);
    __nv_bfloat16 h3 = __float2bfloat16(v.w);
    ((__nv_bfloat162*)H)[2 * i]     = __nv_bfloat162(h0, h1);
    ((__nv_bfloat162*)H)[2 * i + 1] = __nv_bfloat162(h2, h3);
    ((__nv_bfloat162*)L)[2 * i]     = __nv_bfloat162(__float2bfloat16(v.x - __bfloat162float(h0)),
                                                     __float2bfloat16(v.y - __bfloat162float(h1)));
    ((__nv_bfloat162*)L)[2 * i + 1] = __nv_bfloat162(__float2bfloat16(v.z - __bfloat162float(h2)),
                                                     __float2bfloat16(v.w - __bfloat162float(h3)));
}

// W[h][a] -> W^T[a][h], hi/lo split, 3 weights via blockIdx.z
__global__ void wsplit_all(const float* __restrict__ Wv, const float* __restrict__ Wg,
                           const float* __restrict__ Ws,
                           __nv_bfloat16* __restrict__ Ht, __nv_bfloat16* __restrict__ Lt) {
    __shared__ float t[32][33];
    int z = blockIdx.z;
    const float* W = (z == 0) ? Wv : (z == 1) ? Wg : Ws;
    size_t wo = (size_t)z * AA * HH;
    int a0 = blockIdx.x * 32, h0 = blockIdx.y * 32;
    int tx = threadIdx.x, ty = threadIdx.y;
    #pragma unroll
    for (int r = ty; r < 32; r += 8)
        t[r][tx] = W[(size_t)(h0 + r) * AA + a0 + tx];
    __syncthreads();
    #pragma unroll
    for (int r = ty; r < 32; r += 8) {
        float v = t[tx][r];
        __nv_bfloat16 hh = __float2bfloat16(v);
        Ht[wo + (size_t)(a0 + r) * HH + h0 + tx] = hh;
        Lt[wo + (size_t)(a0 + r) * HH + h0 + tx] = __float2bfloat16(v - __bfloat162float(hh));
    }
}

// ---------------------------------------------------------------------------
// Merged bf16x3 tensor GEMM v3: 128m x 64n tiles, ldmatrix frags, 2-block occ.
// grid (8 n-tiles, 65 m-tiles), 256 thr = 8 warps (2 wm x 4 wn), warp 64x16.
// smem per stage: Ah 10240B | Al 10240B | Bh 5120B | Bl 5120B = 30720B; x2 stages.
#define SROW 40
#define STG_B 30720
#define OFF_AL 10240
#define OFF_BH 20480
#define OFF_BL 25600
#define MMA_DSMEM (2 * STG_B)   // 61440

__global__ void __launch_bounds__(256, 2) mma_gemm_all(
        const __nv_bfloat16* __restrict__ Xh, const __nv_bfloat16* __restrict__ Xl,
        const __nv_bfloat16* __restrict__ Wh, const __nv_bfloat16* __restrict__ Wl,
        float* __restrict__ cv, float* __restrict__ cg, float* __restrict__ cs) {
    extern __shared__ __nv_bfloat16 dynsm[];
    uint32_t sb = smem_u32(dynsm);

    int tid = threadIdx.x, wid = tid >> 5, lane = tid & 31;
    int wm = wid >> 2, wn = wid & 3;
    int g = lane >> 2, tig = lane & 3;
    int my = blockIdx.y;
    int n0 = blockIdx.x * 64;

    int arow0; size_t wo; float* C; int crow0;
    if (my < 49)      { arow0 = my * 128;                    wo = 0;                      C = cv; crow0 = my * 128; }
    else if (my < 57) { arow0 = ROWS_ATT + (my - 49) * 128;  wo = (size_t)AA * HH;        C = cg; crow0 = (my - 49) * 128; }
    else              { arow0 = ROWS_ATT + ROWS_HID + (my - 57) * 128; wo = 2 * (size_t)AA * HH; C = cs; crow0 = (my - 57) * 128; }

    float acc[4][2][4];
    #pragma unroll
    for (int i = 0; i < 4; i++)
        #pragma unroll
        for (int j = 0; j < 2; j++)
            #pragma unroll
            for (int q = 0; q < 4; q++) acc[i][j][q] = 0.0f;

    // ldmatrix per-lane intra-tile byte offsets
    int lane15 = lane & 15, lanehi = lane >> 4;
    uint32_t offA[4];
    #pragma unroll
    for (int mf = 0; mf < 4; mf++)
        offA[mf] = (uint32_t)((wm * 64 + mf * 16 + lane15) * SROW * 2 + lanehi * 16);
    uint32_t offB = (uint32_t)((wn * 16 + lane15) * SROW * 2 + lanehi * 16);

    // staging map: r = tid>>2 (0..63), lc = (tid&3)*8 elems
    int lr = tid >> 2, lc = (tid & 3) * 8;

    auto load_stage = [&](int s, int k0) {
        uint32_t base = sb + (uint32_t)s * STG_B;
        uint32_t soff = (uint32_t)(lr * SROW + lc) * 2;
        uint32_t soff2 = (uint32_t)((lr + 64) * SROW + lc) * 2;
        cp16(base + soff,           Xh + (size_t)(arow0 + lr) * GK + k0 + lc);
        cp16(base + soff2,          Xh + (size_t)(arow0 + lr + 64) * GK + k0 + lc);
        cp16(base + OFF_AL + soff,  Xl + (size_t)(arow0 + lr) * GK + k0 + lc);
        cp16(base + OFF_AL + soff2, Xl + (size_t)(arow0 + lr + 64) * GK + k0 + lc);
        cp16(base + OFF_BH + soff,  Wh + wo + (size_t)(n0 + lr) * HH + k0 + lc);
        cp16(base + OFF_BL + soff,  Wl + wo + (size_t)(n0 + lr) * HH + k0 + lc);
    };

    load_stage(0, 0);
    CP_COMMIT();

    const int NIT = GK / 32;
    for (int it = 0; it < NIT; it++) {
        if (it + 1 < NIT) { load_stage((it + 1) & 1, (it + 1) * 32); CP_COMMIT(); CP_WAIT1(); }
        else              { CP_WAIT0(); }
        __syncthreads();

        uint32_t base = sb + (uint32_t)(it & 1) * STG_B;
        #pragma unroll
        for (int ks = 0; ks < 2; ks++) {
            uint32_t ko = (uint32_t)(ks * 32);
            uint32_t aH[4][4], aL[4][4], bH[2][2], bL[2][2];
            #pragma unroll
            for (int mf = 0; mf < 4; mf++) {
                LDSM4(aH[mf][0], aH[mf][1], aH[mf][2], aH[mf][3], base + offA[mf] + ko);
                LDSM4(aL[mf][0], aL[mf][1], aL[mf][2], aL[mf][3], base + OFF_AL + offA[mf] + ko);
            }
            LDSM4(bH[0][0], bH[1][0], bH[0][1], bH[1][1], base + OFF_BH + offB + ko);
            LDSM4(bL[0][0], bL[1][0], bL[0][1], bL[1][1], base + OFF_BL + offB + ko);

            #pragma unroll
            for (int mf = 0; mf < 4; mf++)
                #pragma unroll
                for (int nf = 0; nf < 2; nf++) hmma(acc[mf][nf], aH[mf], bH[nf]);
            #pragma unroll
            for (int mf = 0; mf < 4; mf++)
                #pragma unroll
                for (int nf = 0; nf < 2; nf++) hmma(acc[mf][nf], aH[mf], bL[nf]);
            #pragma unroll
            for (int mf = 0; mf < 4; mf++)
                #pragma unroll
                for (int nf = 0; nf < 2; nf++) hmma(acc[mf][nf], aL[mf], bH[nf]);
        }
        __syncthreads();
    }

    #pragma unroll
    for (int mf = 0; mf < 4; mf++) {
        int row = crow0 + wm * 64 + mf * 16 + g;
        #pragma unroll
        for (int nf = 0; nf < 2; nf++) {
            int col = n0 + wn * 16 + nf * 8 + 2 * tig;
            *(float2*)&C[(size_t)row * AA + col] = make_float2(acc[mf][nf][0], acc[mf][nf][1]);
            *(float2*)&C[(size_t)(row + 8) * AA + col] = make_float2(acc[mf][nf][2], acc[mf][nf][3]);
        }
    }
}

// ---------------------------------------------------------------------------
// zfused v2 (R6-proven): grid (14, 4, 32), 256 thr; warp = one t row.
#define KT 14
#define KTILES (KK / KT)   // 14

__global__ void __launch_bounds__(256) zfused_kernel(const float* __restrict__ wh,
                                                     float* __restrict__ zout) {
    __shared__ float s_cv[KT * 512];   // 28672 B
    __shared__ float s_wh[512];

    int kt = blockIdx.x, tg = blockIdx.y, b = blockIdx.z;
    int tid = threadIdx.x, wid = tid >> 5, lane = tid & 31;
    int t = tg * 8 + wid;
    int row = b * TT + t;

    const float* cvp = g_cv + ((size_t)b * KK + kt * KT) * AA;
    #pragma unroll
    for (int i = tid * 4; i < KT * 512; i += 1024)
        *(float4*)&s_cv[i] = *(const float4*)(cvp + i);
    if (tid * 4 < 512)
        *(float4*)&s_wh[tid * 4] = *(const float4*)(wh + tid * 4);
    __syncthreads();

    float cgr[16], whr[16];
    const float* cgp = g_cg + (size_t)row * AA;
    #pragma unroll
    for (int j = 0; j < 16; j++) {
        cgr[j] = cgp[lane + 32 * j];
        whr[j] = s_wh[lane + 32 * j];
    }

    #pragma unroll
    for (int kk = 0; kk < KT; kk++) {
        const float* cvk = &s_cv[kk * 512];
        float a0 = 0.0f, a1 = 0.0f;
        #pragma unroll
        for (int j = 0; j < 16; j += 2) {
            a0 = fmaf(whr[j],     tanh_mufu(cvk[lane + 32 * j]       + cgr[j]),     a0);
            a1 = fmaf(whr[j + 1], tanh_mufu(cvk[lane + 32 * (j + 1)] + cgr[j + 1]), a1);
        }
        float acc = warp_sum(a0 + a1);
        if (lane == 0)
            zout[(size_t)row * KK + kt * KT + kk] = acc;
    }

    if (kt == 0) {
        const float* cst = g_cs + (size_t)row * AA;
        float a0 = 0.0f, a1 = 0.0f;
        #pragma unroll
        for (int j = 0; j < 16; j += 2) {
            a0 = fmaf(whr[j],     tanh_mufu(cst[lane + 32 * j]       + cgr[j]),     a0);
            a1 = fmaf(whr[j + 1], tanh_mufu(cst[lane + 32 * (j + 1)] + cgr[j + 1]), a1);
        }
        float acc = warp_sum(a0 + a1);
        if (lane == 0) g_zext[row] = acc;
    }
}

// ---------------------------------------------------------------------------
// Softmax over K=196 + beta; one warp per (b,t) row
__global__ void softmax_kernel(float* __restrict__ z, float* __restrict__ beta) {
    const float L2E = 1.4426950408889634f;
    int wid = threadIdx.x >> 5, lane = threadIdx.x & 31;
    int row = blockIdx.x * 8 + wid;
    float* zr = z + (size_t)row * KK;

    float v[7];
    float m = -INFINITY;
    #pragma unroll
    for (int j = 0; j < 7; j++) {
        int k = lane + 32 * j;
        v[j] = (k < KK) ? zr[k] : -INFINITY;
        m = fmaxf(m, v[j]);
    }
    #pragma unroll
    for (int o = 16; o; o >>= 1) m = fmaxf(m, __shfl_xor_sync(0xffffffffu, m, o));

    float s = 0.0f;
    #pragma unroll
    for (int j = 0; j < 7; j++) {
        float e = exp2f((v[j] - m) * L2E);
        v[j] = e;
        s += e;
    }
    s = warp_sum(s);

    float inv = __fdividef(1.0f, s);
    #pragma unroll
    for (int j = 0; j < 7; j++) {
        int k = lane + 32 * j;
        if (k < KK) zr[k] = v[j] * inv;
    }

    if (lane == 0) {
        float ze = g_zext[row];
        float m2 = fmaxf(m, ze);
        float ee = exp2f((ze - m2) * L2E);
        float s2 = s * exp2f((m - m2) * L2E) + ee;
        beta[row] = __fdividef(ee, s2);
    }
}

// ---------------------------------------------------------------------------
// c_hat[b,t,:] = beta*sentinel + (1-beta) * sum_k alpha[b,t,k]*att_feats[b,k,:]
__global__ void ct_kernel(const float* __restrict__ af, const float* __restrict__ sent,
                          const float* __restrict__ alpha, const float* __restrict__ beta,
                          float* __restrict__ chat) {
    __shared__ float s_alpha[8][KK];
    __shared__ float s_beta[8];
    int b = blockIdx.x, tg = blockIdx.y;
    int tid = threadIdx.x;
    int trow0 = b * TT + tg * 8;

    for (int i = tid; i < 8 * KK; i += 256)
        s_alpha[i / KK][i % KK] = alpha[(size_t)(trow0 + i / KK) * KK + i % KK];
    if (tid < 8) s_beta[tid] = beta[trow0 + tid];
    __syncthreads();

    float acc[8][2];
    #pragma unroll
    for (int t = 0; t < 8; t++) { acc[t][0] = 0.0f; acc[t][1] = 0.0f; }

    const float* afb = af + (size_t)b * KK * HH;
    int h2 = tid * 2;
    for (int k = 0; k < KK; k++) {
        float2 vv = *(const float2*)(afb + (size_t)k * HH + h2);
        #pragma unroll
        for (int t = 0; t < 8; t++) {
            float al = s_alpha[t][k];
            acc[t][0] = fmaf(al, vv.x, acc[t][0]);
            acc[t][1] = fmaf(al, vv.y, acc[t][1]);
        }
    }

    #pragma unroll
    for (int t = 0; t < 8; t++) {
        float be = s_beta[t];
        float om = 1.0f - be;
        size_t row = (size_t)(trow0 + t);
        float2 sv = *(const float2*)(sent + row * HH + h2);
        float2 o;
        o.x = be * sv.x + om * acc[t][0];
        o.y = be * sv.y + om * acc[t][1];
        *(float2*)(chat + row * HH + h2) = o;
    }
}

// ---------------------------------------------------------------------------
extern "C" void kernel_launch(void* const* d_in, const int* in_sizes, int n_in,
                              void* d_out, int out_size) {
    const float* att  = (const float*)d_in[0];
    const float* hid  = (const float*)d_in[1];
    const float* sent = (const float*)d_in[2];
    const float* Wv   = (const float*)d_in[3];
    const float* Wg   = (const float*)d_in[4];
    const float* Ws   = (const float*)d_in[5];
    const float* wh   = (const float*)d_in[6];

    float* out   = (float*)d_out;
    float* chat  = out;                               // 524288
    float* alpha = out + (size_t)BB * TT * HH;        // 200704 (z_t staged here)
    float* beta  = alpha + (size_t)BB * TT * KK;      // 1024

    __nv_bfloat16 *xh, *xl, *whp, *wlp;
    float *cv, *cg, *cs;
    cudaGetSymbolAddress((void**)&xh,  g_xh);
    cudaGetSymbolAddress((void**)&xl,  g_xl);
    cudaGetSymbolAddress((void**)&whp, g_wh);
    cudaGetSymbolAddress((void**)&wlp, g_wl);
    cudaGetSymbolAddress((void**)&cv,  g_cv);
    cudaGetSymbolAddress((void**)&cg,  g_cg);
    cudaGetSymbolAddress((void**)&cs,  g_cs);
    cudaFuncSetAttribute(mma_gemm_all, cudaFuncAttributeMaxDynamicSharedMemorySize, MMA_DSMEM);

    // 1. split all activations (att|hid|sent) -> bf16 hi/lo
    split_all<<<(ROWS_ALL * HH / 4 + 255) / 256, 256>>>(att, hid, sent, xh, xl);
    // 2. transpose+split all weights
    wsplit_all<<<dim3(16, 16, 3), dim3(32, 8)>>>(Wv, Wg, Ws, whp, wlp);
    // 3. all three GEMMs, one launch (ldmatrix + cp.async, 2 blocks/SM)
    mma_gemm_all<<<dim3(8, 65), 256, MMA_DSMEM>>>(xh, xl, whp, wlp, cv, cg, cs);
    // 4. fused z_t + z_ext
    zfused_kernel<<<dim3(KTILES, 4, 32), 256>>>(wh, alpha);
    // 5. softmax + beta
    softmax_kernel<<<128, 256>>>(alpha, beta);
    // 6. c_t + sentinel blend
    ct_kernel<<<dim3(32, 4), 256>>>(att, sent, alpha, beta, chat);
}

// round 9
// speedup vs baseline: 1.7338x; 1.6035x over previous
#include <cuda_runtime.h>
#include <cuda_fp16.h>
#include <cstdint>
#include <math.h>

// Problem constants
#define BB 32
#define TT 32
#define KK 196
#define HH 512
#define AA 512
#define GK 512

#define ROWS_ATT (BB * KK)          // 6272
#define ROWS_HID (BB * TT)          // 1024
#define ROWS_ALL (ROWS_ATT + 2 * ROWS_HID)   // 8320

// ---------------------------------------------------------------------------
// Scratch (__device__ globals; no cudaMalloc allowed)
__device__ float g_cv[BB * KK * AA];                 // 12.8 MB
__device__ float g_cg[BB * TT * AA];                 // 2 MB
__device__ float g_cs[BB * TT * AA];                 // 2 MB
__device__ float g_zext[BB * TT];
__device__ __half g_x[ROWS_ALL * HH];                // concat activations fp16
__device__ __half g_w[3 * AA * HH];                  // W^T fp16 (Wv, Wg, Ws)

// ---------------------------------------------------------------------------
__device__ __forceinline__ float tanh_mufu(float x) {
    float y;
    asm("tanh.approx.f32 %0, %1;" : "=f"(y) : "f"(x));
    return y;
}
__device__ __forceinline__ float warp_sum(float v) {
    #pragma unroll
    for (int o = 16; o; o >>= 1) v += __shfl_xor_sync(0xffffffffu, v, o);
    return v;
}

// mma.sync m16n8k16 row.col f32.f16.f16.f32, D == C
__device__ __forceinline__ void hmma(float* c, const uint32_t* a, const uint32_t* b) {
    asm volatile(
        "mma.sync.aligned.m16n8k16.row.col.f32.f16.f16.f32 "
        "{%0,%1,%2,%3}, {%4,%5,%6,%7}, {%8,%9}, {%0,%1,%2,%3};"
        : "+f"(c[0]), "+f"(c[1]), "+f"(c[2]), "+f"(c[3])
        : "r"(a[0]), "r"(a[1]), "r"(a[2]), "r"(a[3]), "r"(b[0]), "r"(b[1]));
}

__device__ __forceinline__ uint32_t smem_u32(const void* p) {
    uint32_t a;
    asm("{ .reg .u64 t; cvta.to.shared.u64 t, %1; cvt.u32.u64 %0, t; }" : "=r"(a) : "l"(p));
    return a;
}
__device__ __forceinline__ void cp16(uint32_t dst, const void* src) {
    asm volatile("cp.async.cg.shared.global [%0], [%1], 16;" :: "r"(dst), "l"(src));
}
#define CP_COMMIT() asm volatile("cp.async.commit_group;" ::: "memory")
#define CP_WAIT1()  asm volatile("cp.async.wait_group 1;" ::: "memory")
#define CP_WAIT0()  asm volatile("cp.async.wait_group 0;" ::: "memory")

// ---------------------------------------------------------------------------
// fp32 -> fp16 cast; all three activations in one launch.
__global__ void split_all(const float* __restrict__ att, const float* __restrict__ hid,
                          const float* __restrict__ sent, __half* __restrict__ H) {
    const int N4 = ROWS_ALL * HH / 4;
    int i = blockIdx.x * blockDim.x + threadIdx.x;
    if (i >= N4) return;
    const float4* src;
    int li;
    if (i < ROWS_ATT * 128)                   { src = (const float4*)att;  li = i; }
    else if (i < (ROWS_ATT + ROWS_HID) * 128) { src = (const float4*)hid;  li = i - ROWS_ATT * 128; }
    else                                      { src = (const float4*)sent; li = i - (ROWS_ATT + ROWS_HID) * 128; }
    float4 v = src[li];
    __half2 p0 = __floats2half2_rn(v.x, v.y);
    __half2 p1 = __floats2half2_rn(v.z, v.w);
    ((__half2*)H)[2 * i]     = p0;
    ((__half2*)H)[2 * i + 1] = p1;
}

// W[h][a] -> W^T[a][h] fp16, 3 weights via blockIdx.z
__global__ void wsplit_all(const float* __restrict__ Wv, const float* __restrict__ Wg,
                           const float* __restrict__ Ws, __half* __restrict__ Ht) {
    __shared__ float t[32][33];
    int z = blockIdx.z;
    const float* W = (z == 0) ? Wv : (z == 1) ? Wg : Ws;
    size_t wo = (size_t)z * AA * HH;
    int a0 = blockIdx.x * 32, h0 = blockIdx.y * 32;
    int tx = threadIdx.x, ty = threadIdx.y;
    #pragma unroll
    for (int r = ty; r < 32; r += 8)
        t[r][tx] = W[(size_t)(h0 + r) * AA + a0 + tx];
    __syncthreads();
    #pragma unroll
    for (int r = ty; r < 32; r += 8)
        Ht[wo + (size_t)(a0 + r) * HH + h0 + tx] = __float2half(t[tx][r]);
}

// ---------------------------------------------------------------------------
// Merged fp16 tensor GEMM (R5-proven geometry): 128x128x32 tiles, 256 thr,
// 8 warps (2x4), warp tile 64x32, SROW=40-padded LDS frags, 2-stage cp.async.
// grid (4 n-tiles, 65 m-tiles): my<49 -> cv, my<57 -> cg, else cs.
#define SROW 40
#define TILE_E (128 * SROW)    // 5120 halves = 10240 B

__global__ void __launch_bounds__(256, 2) mma_gemm_all(
        const __half* __restrict__ X, const __half* __restrict__ Wt,
        float* __restrict__ cv, float* __restrict__ cg, float* __restrict__ cs) {
    __shared__ __half sA[2][TILE_E];
    __shared__ __half sB[2][TILE_E];

    int tid = threadIdx.x, wid = tid >> 5, lane = tid & 31;
    int wm = wid >> 2, wn = wid & 3;
    int g = lane >> 2, tig = lane & 3;
    int my = blockIdx.y;
    int n0 = blockIdx.x * 128;

    int arow0; size_t wo; float* C; int crow0;
    if (my < 49)      { arow0 = my * 128;                    wo = 0;                      C = cv; crow0 = my * 128; }
    else if (my < 57) { arow0 = ROWS_ATT + (my - 49) * 128;  wo = (size_t)AA * HH;        C = cg; crow0 = (my - 49) * 128; }
    else              { arow0 = ROWS_ATT + ROWS_HID + (my - 57) * 128; wo = 2 * (size_t)AA * HH; C = cs; crow0 = (my - 57) * 128; }

    float acc[4][4][4];
    #pragma unroll
    for (int i = 0; i < 4; i++)
        #pragma unroll
        for (int j = 0; j < 4; j++)
            #pragma unroll
            for (int q = 0; q < 4; q++) acc[i][j][q] = 0.0f;

    int lr = tid >> 2, lc = (tid & 3) * 8;   // row 0..63, col 0/8/16/24
    uint32_t sbA = smem_u32(sA), sbB = smem_u32(sB);

    auto load_stage = [&](int s, int k0) {
        uint32_t soff  = (uint32_t)(lr * SROW + lc) * 2;
        uint32_t soff2 = (uint32_t)((lr + 64) * SROW + lc) * 2;
        uint32_t bA = sbA + (uint32_t)s * (TILE_E * 2);
        uint32_t bB = sbB + (uint32_t)s * (TILE_E * 2);
        cp16(bA + soff,  X + (size_t)(arow0 + lr) * GK + k0 + lc);
        cp16(bA + soff2, X + (size_t)(arow0 + lr + 64) * GK + k0 + lc);
        cp16(bB + soff,  Wt + wo + (size_t)(n0 + lr) * HH + k0 + lc);
        cp16(bB + soff2, Wt + wo + (size_t)(n0 + lr + 64) * HH + k0 + lc);
    };

    load_stage(0, 0);
    CP_COMMIT();

    const int NIT = GK / 32;   // 16
    for (int it = 0; it < NIT; it++) {
        if (it + 1 < NIT) { load_stage((it + 1) & 1, (it + 1) * 32); CP_COMMIT(); CP_WAIT1(); }
        else              { CP_WAIT0(); }
        __syncthreads();

        const __half* A = sA[it & 1];
        const __half* B = sB[it & 1];

        #pragma unroll
        for (int ks = 0; ks < 2; ks++) {
            int c0 = ks * 16 + 2 * tig;
            uint32_t aF[4][4], bF[4][2];
            #pragma unroll
            for (int mf = 0; mf < 4; mf++) {
                int mr = wm * 64 + mf * 16;
                aF[mf][0] = *(const uint32_t*)&A[(mr + g) * SROW + c0];
                aF[mf][1] = *(const uint32_t*)&A[(mr + g + 8) * SROW + c0];
                aF[mf][2] = *(const uint32_t*)&A[(mr + g) * SROW + c0 + 8];
                aF[mf][3] = *(const uint32_t*)&A[(mr + g + 8) * SROW + c0 + 8];
            }
            #pragma unroll
            for (int nf = 0; nf < 4; nf++) {
                int nr = wn * 32 + nf * 8;
                bF[nf][0] = *(const uint32_t*)&B[(nr + g) * SROW + c0];
                bF[nf][1] = *(const uint32_t*)&B[(nr + g) * SROW + c0 + 8];
            }
            #pragma unroll
            for (int mf = 0; mf < 4; mf++)
                #pragma unroll
                for (int nf = 0; nf < 4; nf++) hmma(acc[mf][nf], aF[mf], bF[nf]);
        }
        __syncthreads();
    }

    #pragma unroll
    for (int mf = 0; mf < 4; mf++) {
        int row = crow0 + wm * 64 + mf * 16 + g;
        #pragma unroll
        for (int nf = 0; nf < 4; nf++) {
            int col = n0 + wn * 32 + nf * 8 + 2 * tig;
            *(float2*)&C[(size_t)row * AA + col] = make_float2(acc[mf][nf][0], acc[mf][nf][1]);
            *(float2*)&C[(size_t)(row + 8) * AA + col] = make_float2(acc[mf][nf][2], acc[mf][nf][3]);
        }
    }
}

// ---------------------------------------------------------------------------
// zfused v2 (R6-proven): grid (14, 4, 32), 256 thr; warp = one t row.
#define KT 14
#define KTILES (KK / KT)   // 14

__global__ void __launch_bounds__(256) zfused_kernel(const float* __restrict__ wh,
                                                     float* __restrict__ zout) {
    __shared__ float s_cv[KT * 512];   // 28672 B
    __shared__ float s_wh[512];

    int kt = blockIdx.x, tg = blockIdx.y, b = blockIdx.z;
    int tid = threadIdx.x, wid = tid >> 5, lane = tid & 31;
    int t = tg * 8 + wid;
    int row = b * TT + t;

    const float* cvp = g_cv + ((size_t)b * KK + kt * KT) * AA;
    #pragma unroll
    for (int i = tid * 4; i < KT * 512; i += 1024)
        *(float4*)&s_cv[i] = *(const float4*)(cvp + i);
    if (tid * 4 < 512)
        *(float4*)&s_wh[tid * 4] = *(const float4*)(wh + tid * 4);
    __syncthreads();

    float cgr[16], whr[16];
    const float* cgp = g_cg + (size_t)row * AA;
    #pragma unroll
    for (int j = 0; j < 16; j++) {
        cgr[j] = cgp[lane + 32 * j];
        whr[j] = s_wh[lane + 32 * j];
    }

    #pragma unroll
    for (int kk = 0; kk < KT; kk++) {
        const float* cvk = &s_cv[kk * 512];
        float a0 = 0.0f, a1 = 0.0f;
        #pragma unroll
        for (int j = 0; j < 16; j += 2) {
            a0 = fmaf(whr[j],     tanh_mufu(cvk[lane + 32 * j]       + cgr[j]),     a0);
            a1 = fmaf(whr[j + 1], tanh_mufu(cvk[lane + 32 * (j + 1)] + cgr[j + 1]), a1);
        }
        float acc = warp_sum(a0 + a1);
        if (lane == 0)
            zout[(size_t)row * KK + kt * KT + kk] = acc;
    }

    if (kt == 0) {
        const float* cst = g_cs + (size_t)row * AA;
        float a0 = 0.0f, a1 = 0.0f;
        #pragma unroll
        for (int j = 0; j < 16; j += 2) {
            a0 = fmaf(whr[j],     tanh_mufu(cst[lane + 32 * j]       + cgr[j]),     a0);
            a1 = fmaf(whr[j + 1], tanh_mufu(cst[lane + 32 * (j + 1)] + cgr[j + 1]), a1);
        }
        float acc = warp_sum(a0 + a1);
        if (lane == 0) g_zext[row] = acc;
    }
}

// ---------------------------------------------------------------------------
// Softmax over K=196 + beta; one warp per (b,t) row
__global__ void softmax_kernel(float* __restrict__ z, float* __restrict__ beta) {
    const float L2E = 1.4426950408889634f;
    int wid = threadIdx.x >> 5, lane = threadIdx.x & 31;
    int row = blockIdx.x * 8 + wid;
    float* zr = z + (size_t)row * KK;

    float v[7];
    float m = -INFINITY;
    #pragma unroll
    for (int j = 0; j < 7; j++) {
        int k = lane + 32 * j;
        v[j] = (k < KK) ? zr[k] : -INFINITY;
        m = fmaxf(m, v[j]);
    }
    #pragma unroll
    for (int o = 16; o; o >>= 1) m = fmaxf(m, __shfl_xor_sync(0xffffffffu, m, o));

    float s = 0.0f;
    #pragma unroll
    for (int j = 0; j < 7; j++) {
        float e = exp2f((v[j] - m) * L2E);
        v[j] = e;
        s += e;
    }
    s = warp_sum(s);

    float inv = __fdividef(1.0f, s);
    #pragma unroll
    for (int j = 0; j < 7; j++) {
        int k = lane + 32 * j;
        if (k < KK) zr[k] = v[j] * inv;
    }

    if (lane == 0) {
        float ze = g_zext[row];
        float m2 = fmaxf(m, ze);
        float ee = exp2f((ze - m2) * L2E);
        float s2 = s * exp2f((m - m2) * L2E) + ee;
        beta[row] = __fdividef(ee, s2);
    }
}

// ---------------------------------------------------------------------------
// c_hat[b,t,:] = beta*sentinel + (1-beta) * sum_k alpha[b,t,k]*att_feats[b,k,:]
__global__ void ct_kernel(const float* __restrict__ af, const float* __restrict__ sent,
                          const float* __restrict__ alpha, const float* __restrict__ beta,
                          float* __restrict__ chat) {
    __shared__ float s_alpha[8][KK];
    __shared__ float s_beta[8];
    int b = blockIdx.x, tg = blockIdx.y;
    int tid = threadIdx.x;
    int trow0 = b * TT + tg * 8;

    for (int i = tid; i < 8 * KK; i += 256)
        s_alpha[i / KK][i % KK] = alpha[(size_t)(trow0 + i / KK) * KK + i % KK];
    if (tid < 8) s_beta[tid] = beta[trow0 + tid];
    __syncthreads();

    float acc[8][2];
    #pragma unroll
    for (int t = 0; t < 8; t++) { acc[t][0] = 0.0f; acc[t][1] = 0.0f; }

    const float* afb = af + (size_t)b * KK * HH;
    int h2 = tid * 2;
    for (int k = 0; k < KK; k++) {
        float2 vv = *(const float2*)(afb + (size_t)k * HH + h2);
        #pragma unroll
        for (int t = 0; t < 8; t++) {
            float al = s_alpha[t][k];
            acc[t][0] = fmaf(al, vv.x, acc[t][0]);
            acc[t][1] = fmaf(al, vv.y, acc[t][1]);
        }
    }

    #pragma unroll
    for (int t = 0; t < 8; t++) {
        float be = s_beta[t];
        float om = 1.0f - be;
        size_t row = (size_t)(trow0 + t);
        float2 sv = *(const float2*)(sent + row * HH + h2);
        float2 o;
        o.x = be * sv.x + om * acc[t][0];
        o.y = be * sv.y + om * acc[t][1];
        *(float2*)(chat + row * HH + h2) = o;
    }
}

// ---------------------------------------------------------------------------
extern "C" void kernel_launch(void* const* d_in, const int* in_sizes, int n_in,
                              void* d_out, int out_size) {
    const float* att  = (const float*)d_in[0];
    const float* hid  = (const float*)d_in[1];
    const float* sent = (const float*)d_in[2];
    const float* Wv   = (const float*)d_in[3];
    const float* Wg   = (const float*)d_in[4];
    const float* Ws   = (const float*)d_in[5];
    const float* wh   = (const float*)d_in[6];

    float* out   = (float*)d_out;
    float* chat  = out;                               // 524288
    float* alpha = out + (size_t)BB * TT * HH;        // 200704 (z_t staged here)
    float* beta  = alpha + (size_t)BB * TT * KK;      // 1024

    __half *x, *w;
    float *cv, *cg, *cs;
    cudaGetSymbolAddress((void**)&x,  g_x);
    cudaGetSymbolAddress((void**)&w,  g_w);
    cudaGetSymbolAddress((void**)&cv, g_cv);
    cudaGetSymbolAddress((void**)&cg, g_cg);
    cudaGetSymbolAddress((void**)&cs, g_cs);

    // 1. cast all activations (att|hid|sent) -> fp16
    split_all<<<(ROWS_ALL * HH / 4 + 255) / 256, 256>>>(att, hid, sent, x);
    // 2. transpose+cast all weights
    wsplit_all<<<dim3(16, 16, 3), dim3(32, 8)>>>(Wv, Wg, Ws, w);
    // 3. all three GEMMs, one launch (fp16 x1, 2-stage cp.async)
    mma_gemm_all<<<dim3(4, 65), 256>>>(x, w, cv, cg, cs);
    // 4. fused z_t + z_ext
    zfused_kernel<<<dim3(KTILES, 4, 32), 256>>>(wh, alpha);
    // 5. softmax + beta
    softmax_kernel<<<128, 256>>>(alpha, beta);
    // 6. c_t + sentinel blend
    ct_kernel<<<dim3(32, 4), 256>>>(att, sent, alpha, beta, chat);
}

// round 10
// speedup vs baseline: 1.9795x; 1.1417x over previous
#include <cuda_runtime.h>
#include <cuda_fp16.h>
#include <cstdint>
#include <math.h>

// Problem constants
#define BB 32
#define TT 32
#define KK 196
#define HH 512
#define AA 512
#define GK 512

#define ROWS_ATT (BB * KK)          // 6272
#define ROWS_HID (BB * TT)          // 1024
#define ROWS_ALL (ROWS_ATT + 2 * ROWS_HID)   // 8320

// ---------------------------------------------------------------------------
// Scratch (__device__ globals; no cudaMalloc allowed)
__device__ __half g_cvh[BB * KK * AA];               // cv in fp16, 6.4 MB
__device__ float g_cg[BB * TT * AA];                 // 2 MB
__device__ float g_cs[BB * TT * AA];                 // 2 MB
__device__ __half g_x[ROWS_ALL * HH];                // concat activations fp16
__device__ __half g_w[3 * AA * HH];                  // W^T fp16 (Wv, Wg, Ws)

// ---------------------------------------------------------------------------
__device__ __forceinline__ float tanh_mufu(float x) {
    float y;
    asm("tanh.approx.f32 %0, %1;" : "=f"(y) : "f"(x));
    return y;
}
__device__ __forceinline__ __half2 tanh_h2(__half2 x) {
    uint32_t u = *(uint32_t*)&x, r;
    asm("tanh.approx.f16x2 %0, %1;" : "=r"(r) : "r"(u));
    return *(__half2*)&r;
}
__device__ __forceinline__ float warp_sum(float v) {
    #pragma unroll
    for (int o = 16; o; o >>= 1) v += __shfl_xor_sync(0xffffffffu, v, o);
    return v;
}

// mma.sync m16n8k16 row.col f32.f16.f16.f32, D == C
__device__ __forceinline__ void hmma(float* c, const uint32_t* a, const uint32_t* b) {
    asm volatile(
        "mma.sync.aligned.m16n8k16.row.col.f32.f16.f16.f32 "
        "{%0,%1,%2,%3}, {%4,%5,%6,%7}, {%8,%9}, {%0,%1,%2,%3};"
        : "+f"(c[0]), "+f"(c[1]), "+f"(c[2]), "+f"(c[3])
        : "r"(a[0]), "r"(a[1]), "r"(a[2]), "r"(a[3]), "r"(b[0]), "r"(b[1]));
}

__device__ __forceinline__ uint32_t smem_u32(const void* p) {
    uint32_t a;
    asm("{ .reg .u64 t; cvta.to.shared.u64 t, %1; cvt.u32.u64 %0, t; }" : "=r"(a) : "l"(p));
    return a;
}
__device__ __forceinline__ void cp16(uint32_t dst, const void* src) {
    asm volatile("cp.async.cg.shared.global [%0], [%1], 16;" :: "r"(dst), "l"(src));
}
#define CP_COMMIT() asm volatile("cp.async.commit_group;" ::: "memory")
#define CP_WAIT1()  asm volatile("cp.async.wait_group 1;" ::: "memory")
#define CP_WAIT0()  asm volatile("cp.async.wait_group 0;" ::: "memory")

// ---------------------------------------------------------------------------
// prep: activation fp16 cast (blocks [0, NSPLIT)) + weight transpose/cast.
#define NSPLIT ((ROWS_ALL * HH / 4 + 255) / 256)   // 4160

__global__ void prep_kernel(const float* __restrict__ att, const float* __restrict__ hid,
                            const float* __restrict__ sent,
                            const float* __restrict__ Wv, const float* __restrict__ Wg,
                            const float* __restrict__ Ws) {
    int tid = threadIdx.x;
    if (blockIdx.x < NSPLIT) {
        const int N4 = ROWS_ALL * HH / 4;
        int i = blockIdx.x * 256 + tid;
        if (i >= N4) return;
        const float4* src;
        int li;
        if (i < ROWS_ATT * 128)                   { src = (const float4*)att;  li = i; }
        else if (i < (ROWS_ATT + ROWS_HID) * 128) { src = (const float4*)hid;  li = i - ROWS_ATT * 128; }
        else                                      { src = (const float4*)sent; li = i - (ROWS_ATT + ROWS_HID) * 128; }
        float4 v = src[li];
        ((__half2*)g_x)[2 * i]     = __floats2half2_rn(v.x, v.y);
        ((__half2*)g_x)[2 * i + 1] = __floats2half2_rn(v.z, v.w);
    } else {
        __shared__ float t[32][33];
        int zb = blockIdx.x - NSPLIT;
        int z = zb >> 8, rem = zb & 255;
        const float* W = (z == 0) ? Wv : (z == 1) ? Wg : Ws;
        size_t wo = (size_t)z * AA * HH;
        int a0 = (rem & 15) * 32, h0 = (rem >> 4) * 32;
        int tx = tid & 31, ty = tid >> 5;
        #pragma unroll
        for (int r = ty; r < 32; r += 8)
            t[r][tx] = W[(size_t)(h0 + r) * AA + a0 + tx];
        __syncthreads();
        #pragma unroll
        for (int r = ty; r < 32; r += 8)
            g_w[wo + (size_t)(a0 + r) * HH + h0 + tx] = __float2half(t[tx][r]);
    }
}

// ---------------------------------------------------------------------------
// Merged fp16 tensor GEMM (R5/R9-proven geometry): 128x128x32 tiles, 256 thr,
// 8 warps (2x4), warp tile 64x32, SROW=40-padded LDS frags, 2-stage cp.async.
// grid (4 n-tiles, 65 m-tiles): my<49 -> cv (HALF out), my<57 -> cg, else cs.
#define SROW 40
#define TILE_E (128 * SROW)    // 5120 halves = 10240 B

__global__ void __launch_bounds__(256, 2) mma_gemm_all(
        const __half* __restrict__ X, const __half* __restrict__ Wt,
        __half* __restrict__ cvh, float* __restrict__ cg, float* __restrict__ cs) {
    __shared__ __half sA[2][TILE_E];
    __shared__ __half sB[2][TILE_E];

    int tid = threadIdx.x, wid = tid >> 5, lane = tid & 31;
    int wm = wid >> 2, wn = wid & 3;
    int g = lane >> 2, tig = lane & 3;
    int my = blockIdx.y;
    int n0 = blockIdx.x * 128;

    int arow0; size_t wo; float* C; int crow0; bool halfout;
    if (my < 49)      { arow0 = my * 128;                    wo = 0;                      C = nullptr; crow0 = my * 128; halfout = true; }
    else if (my < 57) { arow0 = ROWS_ATT + (my - 49) * 128;  wo = (size_t)AA * HH;        C = cg; crow0 = (my - 49) * 128; halfout = false; }
    else              { arow0 = ROWS_ATT + ROWS_HID + (my - 57) * 128; wo = 2 * (size_t)AA * HH; C = cs; crow0 = (my - 57) * 128; halfout = false; }

    float acc[4][4][4];
    #pragma unroll
    for (int i = 0; i < 4; i++)
        #pragma unroll
        for (int j = 0; j < 4; j++)
            #pragma unroll
            for (int q = 0; q < 4; q++) acc[i][j][q] = 0.0f;

    int lr = tid >> 2, lc = (tid & 3) * 8;   // row 0..63, col 0/8/16/24
    uint32_t sbA = smem_u32(sA), sbB = smem_u32(sB);

    auto load_stage = [&](int s, int k0) {
        uint32_t soff  = (uint32_t)(lr * SROW + lc) * 2;
        uint32_t soff2 = (uint32_t)((lr + 64) * SROW + lc) * 2;
        uint32_t bA = sbA + (uint32_t)s * (TILE_E * 2);
        uint32_t bB = sbB + (uint32_t)s * (TILE_E * 2);
        cp16(bA + soff,  X + (size_t)(arow0 + lr) * GK + k0 + lc);
        cp16(bA + soff2, X + (size_t)(arow0 + lr + 64) * GK + k0 + lc);
        cp16(bB + soff,  Wt + wo + (size_t)(n0 + lr) * HH + k0 + lc);
        cp16(bB + soff2, Wt + wo + (size_t)(n0 + lr + 64) * HH + k0 + lc);
    };

    load_stage(0, 0);
    CP_COMMIT();

    const int NIT = GK / 32;   // 16
    for (int it = 0; it < NIT; it++) {
        if (it + 1 < NIT) { load_stage((it + 1) & 1, (it + 1) * 32); CP_COMMIT(); CP_WAIT1(); }
        else              { CP_WAIT0(); }
        __syncthreads();

        const __half* A = sA[it & 1];
        const __half* B = sB[it & 1];

        #pragma unroll
        for (int ks = 0; ks < 2; ks++) {
            int c0 = ks * 16 + 2 * tig;
            uint32_t aF[4][4], bF[4][2];
            #pragma unroll
            for (int mf = 0; mf < 4; mf++) {
                int mr = wm * 64 + mf * 16;
                aF[mf][0] = *(const uint32_t*)&A[(mr + g) * SROW + c0];
                aF[mf][1] = *(const uint32_t*)&A[(mr + g + 8) * SROW + c0];
                aF[mf][2] = *(const uint32_t*)&A[(mr + g) * SROW + c0 + 8];
                aF[mf][3] = *(const uint32_t*)&A[(mr + g + 8) * SROW + c0 + 8];
            }
            #pragma unroll
            for (int nf = 0; nf < 4; nf++) {
                int nr = wn * 32 + nf * 8;
                bF[nf][0] = *(const uint32_t*)&B[(nr + g) * SROW + c0];
                bF[nf][1] = *(const uint32_t*)&B[(nr + g) * SROW + c0 + 8];
            }
            #pragma unroll
            for (int mf = 0; mf < 4; mf++)
                #pragma unroll
                for (int nf = 0; nf < 4; nf++) hmma(acc[mf][nf], aF[mf], bF[nf]);
        }
        __syncthreads();
    }

    if (halfout) {
        __half2* Ch = (__half2*)cvh;
        #pragma unroll
        for (int mf = 0; mf < 4; mf++) {
            int row = crow0 + wm * 64 + mf * 16 + g;
            #pragma unroll
            for (int nf = 0; nf < 4; nf++) {
                int colp = (n0 + wn * 32 + nf * 8 + 2 * tig) >> 1;   // half2 index
                Ch[(size_t)row * 256 + colp]       = __floats2half2_rn(acc[mf][nf][0], acc[mf][nf][1]);
                Ch[(size_t)(row + 8) * 256 + colp] = __floats2half2_rn(acc[mf][nf][2], acc[mf][nf][3]);
            }
        }
    } else {
        #pragma unroll
        for (int mf = 0; mf < 4; mf++) {
            int row = crow0 + wm * 64 + mf * 16 + g;
            #pragma unroll
            for (int nf = 0; nf < 4; nf++) {
                int col = n0 + wn * 32 + nf * 8 + 2 * tig;
                *(float2*)&C[(size_t)row * AA + col] = make_float2(acc[mf][nf][0], acc[mf][nf][1]);
                *(float2*)&C[(size_t)(row + 8) * AA + col] = make_float2(acc[mf][nf][2], acc[mf][nf][3]);
            }
        }
    }
}

// ---------------------------------------------------------------------------
// zfused v3: f16x2 tanh. grid (14, 4, 32), 256 thr; warp = one t row.
// cv tile in smem as half2; cg packed to half2 regs; fp32 accumulation.
#define KT 14
#define KTILES (KK / KT)   // 14

__global__ void __launch_bounds__(256) zfused_kernel(const float* __restrict__ wh,
                                                     float* __restrict__ zout) {
    __shared__ __half2 s_cv[KT * 256];   // 14336 B

    int kt = blockIdx.x, tg = blockIdx.y, b = blockIdx.z;
    int tid = threadIdx.x, wid = tid >> 5, lane = tid & 31;
    int t = tg * 8 + wid;
    int row = b * TT + t;

    // stage cv tile (half): 896 uint4
    const uint4* cvp = (const uint4*)(g_cvh + ((size_t)b * KK + kt * KT) * AA);
    for (int i = tid; i < 896; i += 256)
        ((uint4*)s_cv)[i] = cvp[i];
    __syncthreads();

    // cg (half2) + wh (float2) register-resident; lane owns a-pairs 2*lane + 64*j
    __half2 cgh[8];
    float2 whr[8];
    const float* cgp = g_cg + (size_t)row * AA;
    #pragma unroll
    for (int j = 0; j < 8; j++) {
        float2 c = *(const float2*)&cgp[2 * (lane + 32 * j)];
        cgh[j] = __floats2half2_rn(c.x, c.y);
        whr[j] = *(const float2*)&wh[2 * (lane + 32 * j)];
    }

    #pragma unroll
    for (int kk = 0; kk < KT; kk++) {
        const __half2* cvk = s_cv + kk * 256;
        float a0 = 0.0f, a1 = 0.0f;
        #pragma unroll
        for (int j = 0; j < 8; j += 2) {
            __half2 s0 = __hadd2(cvk[lane + 32 * j],       cgh[j]);
            __half2 s1 = __hadd2(cvk[lane + 32 * (j + 1)], cgh[j + 1]);
            float2 f0 = __half22float2(tanh_h2(s0));
            float2 f1 = __half22float2(tanh_h2(s1));
            a0 = fmaf(whr[j].x,     f0.x, a0);
            a1 = fmaf(whr[j].y,     f0.y, a1);
            a0 = fmaf(whr[j + 1].x, f1.x, a0);
            a1 = fmaf(whr[j + 1].y, f1.y, a1);
        }
        float acc = warp_sum(a0 + a1);
        if (lane == 0)
            zout[(size_t)row * KK + kt * KT + kk] = acc;
    }
}

// ---------------------------------------------------------------------------
// FUSED softmax (+z_ext) + c_t blend. grid (32 b, 4 tg), 256 thr.
// Phase 1: warp w handles row trow0+w: z_ext, softmax -> s_alpha + global, beta.
// Phase 2: blend (reads s_alpha).
__global__ void __launch_bounds__(256) softmax_ct_kernel(
        const float* __restrict__ af, const float* __restrict__ sent,
        const float* __restrict__ wh,
        float* __restrict__ alpha, float* __restrict__ beta,
        float* __restrict__ chat) {
    __shared__ float s_alpha[8][KK];
    __shared__ float s_beta[8];
    const float L2E = 1.4426950408889634f;

    int b = blockIdx.x, tg = blockIdx.y;
    int tid = threadIdx.x, wid = tid >> 5, lane = tid & 31;
    int trow0 = b * TT + tg * 8;

    // ---- Phase 1: softmax + zext + beta, one warp per row ----
    {
        int row = trow0 + wid;
        float* zr = alpha + (size_t)row * KK;

        // z_ext = sum_a wh[a]*tanh(cs+cg) (f32 tanh; only 0.5M total — cheap)
        float ze;
        {
            const float* cs = g_cs + (size_t)row * AA;
            const float* cg = g_cg + (size_t)row * AA;
            float a0 = 0.0f;
            #pragma unroll
            for (int j = 0; j < 4; j++) {
                int i4 = (j * 32 + lane) * 4;
                float4 c1 = *(const float4*)&cs[i4];
                float4 c2 = *(const float4*)&cg[i4];
                float4 w4 = *(const float4*)&wh[i4];
                a0 = fmaf(w4.x, tanh_mufu(c1.x + c2.x), a0);
                a0 = fmaf(w4.y, tanh_mufu(c1.y + c2.y), a0);
                a0 = fmaf(w4.z, tanh_mufu(c1.z + c2.z), a0);
                a0 = fmaf(w4.w, tanh_mufu(c1.w + c2.w), a0);
            }
            ze = warp_sum(a0);
        }

        float v[7];
        float m = -INFINITY;
        #pragma unroll
        for (int j = 0; j < 7; j++) {
            int k = lane + 32 * j;
            v[j] = (k < KK) ? zr[k] : -INFINITY;
            m = fmaxf(m, v[j]);
        }
        #pragma unroll
        for (int o = 16; o; o >>= 1) m = fmaxf(m, __shfl_xor_sync(0xffffffffu, m, o));

        float s = 0.0f;
        #pragma unroll
        for (int j = 0; j < 7; j++) {
            float e = exp2f((v[j] - m) * L2E);
            v[j] = e;
            s += e;
        }
        s = warp_sum(s);

        float inv = __fdividef(1.0f, s);
        #pragma unroll
        for (int j = 0; j < 7; j++) {
            int k = lane + 32 * j;
            if (k < KK) {
                float a = v[j] * inv;
                zr[k] = a;                // alpha output
                s_alpha[wid][k] = a;      // for phase 2
            }
        }

        if (lane == 0) {
            float m2 = fmaxf(m, ze);
            float ee = exp2f((ze - m2) * L2E);
            float s2 = s * exp2f((m - m2) * L2E) + ee;
            float be = __fdividef(ee, s2);
            beta[row] = be;
            s_beta[wid] = be;
        }
    }
    __syncthreads();

    // ---- Phase 2: c_hat = beta*sent + (1-beta)*sum_k alpha*af ----
    float acc[8][2];
    #pragma unroll
    for (int t = 0; t < 8; t++) { acc[t][0] = 0.0f; acc[t][1] = 0.0f; }

    const float* afb = af + (size_t)b * KK * HH;
    int h2 = tid * 2;
    for (int k = 0; k < KK; k++) {
        float2 vv = *(const float2*)(afb + (size_t)k * HH + h2);
        #pragma unroll
        for (int t = 0; t < 8; t++) {
            float al = s_alpha[t][k];
            acc[t][0] = fmaf(al, vv.x, acc[t][0]);
            acc[t][1] = fmaf(al, vv.y, acc[t][1]);
        }
    }

    #pragma unroll
    for (int t = 0; t < 8; t++) {
        float be = s_beta[t];
        float om = 1.0f - be;
        size_t row = (size_t)(trow0 + t);
        float2 sv = *(const float2*)(sent + row * HH + h2);
        float2 o;
        o.x = be * sv.x + om * acc[t][0];
        o.y = be * sv.y + om * acc[t][1];
        *(float2*)(chat + row * HH + h2) = o;
    }
}

// ---------------------------------------------------------------------------
extern "C" void kernel_launch(void* const* d_in, const int* in_sizes, int n_in,
                              void* d_out, int out_size) {
    const float* att  = (const float*)d_in[0];
    const float* hid  = (const float*)d_in[1];
    const float* sent = (const float*)d_in[2];
    const float* Wv   = (const float*)d_in[3];
    const float* Wg   = (const float*)d_in[4];
    const float* Ws   = (const float*)d_in[5];
    const float* wh   = (const float*)d_in[6];

    float* out   = (float*)d_out;
    float* chat  = out;                               // 524288
    float* alpha = out + (size_t)BB * TT * HH;        // 200704 (z_t staged here)
    float* beta  = alpha + (size_t)BB * TT * KK;      // 1024

    __half *x, *w, *cvh;
    float *cg, *cs;
    cudaGetSymbolAddress((void**)&x,   g_x);
    cudaGetSymbolAddress((void**)&w,   g_w);
    cudaGetSymbolAddress((void**)&cvh, g_cvh);
    cudaGetSymbolAddress((void**)&cg,  g_cg);
    cudaGetSymbolAddress((void**)&cs,  g_cs);

    // 1. prep: cast activations + transpose/cast weights (one launch)
    prep_kernel<<<NSPLIT + 768, 256>>>(att, hid, sent, Wv, Wg, Ws);
    // 2. all three GEMMs (fp16, cv -> half2 output)
    mma_gemm_all<<<dim3(4, 65), 256>>>(x, w, cvh, cg, cs);
    // 3. fused z_t (f16x2 tanh)
    zfused_kernel<<<dim3(KTILES, 4, 32), 256>>>(wh, alpha);
    // 4. fused softmax + z_ext + beta + blend
    softmax_ct_kernel<<<dim3(32, 4), 256>>>(att, sent, wh, alpha, beta, chat);
}

// round 11
// speedup vs baseline: 1.9962x; 1.0085x over previous
#include <cuda_runtime.h>
#include <cuda_fp16.h>
#include <cstdint>
#include <math.h>

// Problem constants
#define BB 32
#define TT 32
#define KK 196
#define HH 512
#define AA 512
#define GK 512

#define ROWS_ATT (BB * KK)          // 6272
#define ROWS_HID (BB * TT)          // 1024
#define ROWS_ALL (ROWS_ATT + 2 * ROWS_HID)   // 8320

// ---------------------------------------------------------------------------
// Scratch (__device__ globals; no cudaMalloc allowed)
__device__ __half g_cvh[BB * KK * AA];               // cv in fp16, 6.4 MB
__device__ float g_cg[BB * TT * AA];                 // 2 MB
__device__ float g_cs[BB * TT * AA];                 // 2 MB
__device__ __half g_x[ROWS_ALL * HH];                // concat activations fp16
__device__ __half g_w[3 * AA * HH];                  // W^T fp16 (Wv, Wg, Ws)

// ---------------------------------------------------------------------------
__device__ __forceinline__ float tanh_mufu(float x) {
    float y;
    asm("tanh.approx.f32 %0, %1;" : "=f"(y) : "f"(x));
    return y;
}
__device__ __forceinline__ __half2 tanh_h2(__half2 x) {
    uint32_t u = *(uint32_t*)&x, r;
    asm("tanh.approx.f16x2 %0, %1;" : "=r"(r) : "r"(u));
    return *(__half2*)&r;
}
__device__ __forceinline__ float warp_sum(float v) {
    #pragma unroll
    for (int o = 16; o; o >>= 1) v += __shfl_xor_sync(0xffffffffu, v, o);
    return v;
}

// mma.sync m16n8k16 row.col f32.f16.f16.f32, D == C
__device__ __forceinline__ void hmma(float* c, const uint32_t* a, const uint32_t* b) {
    asm volatile(
        "mma.sync.aligned.m16n8k16.row.col.f32.f16.f16.f32 "
        "{%0,%1,%2,%3}, {%4,%5,%6,%7}, {%8,%9}, {%0,%1,%2,%3};"
        : "+f"(c[0]), "+f"(c[1]), "+f"(c[2]), "+f"(c[3])
        : "r"(a[0]), "r"(a[1]), "r"(a[2]), "r"(a[3]), "r"(b[0]), "r"(b[1]));
}

__device__ __forceinline__ uint32_t smem_u32(const void* p) {
    uint32_t a;
    asm("{ .reg .u64 t; cvta.to.shared.u64 t, %1; cvt.u32.u64 %0, t; }" : "=r"(a) : "l"(p));
    return a;
}
__device__ __forceinline__ void cp16(uint32_t dst, const void* src) {
    asm volatile("cp.async.cg.shared.global [%0], [%1], 16;" :: "r"(dst), "l"(src));
}
#define CP_COMMIT() asm volatile("cp.async.commit_group;" ::: "memory")
#define CP_WAIT1()  asm volatile("cp.async.wait_group 1;" ::: "memory")
#define CP_WAIT0()  asm volatile("cp.async.wait_group 0;" ::: "memory")

// ---------------------------------------------------------------------------
// prep: activation fp16 cast (blocks [0, NSPLIT)) + weight transpose/cast.
#define NSPLIT ((ROWS_ALL * HH / 4 + 255) / 256)   // 4160

__global__ void prep_kernel(const float* __restrict__ att, const float* __restrict__ hid,
                            const float* __restrict__ sent,
                            const float* __restrict__ Wv, const float* __restrict__ Wg,
                            const float* __restrict__ Ws) {
    int tid = threadIdx.x;
    if (blockIdx.x < NSPLIT) {
        const int N4 = ROWS_ALL * HH / 4;
        int i = blockIdx.x * 256 + tid;
        if (i >= N4) return;
        const float4* src;
        int li;
        if (i < ROWS_ATT * 128)                   { src = (const float4*)att;  li = i; }
        else if (i < (ROWS_ATT + ROWS_HID) * 128) { src = (const float4*)hid;  li = i - ROWS_ATT * 128; }
        else                                      { src = (const float4*)sent; li = i - (ROWS_ATT + ROWS_HID) * 128; }
        float4 v = src[li];
        ((__half2*)g_x)[2 * i]     = __floats2half2_rn(v.x, v.y);
        ((__half2*)g_x)[2 * i + 1] = __floats2half2_rn(v.z, v.w);
    } else {
        __shared__ float t[32][33];
        int zb = blockIdx.x - NSPLIT;
        int z = zb >> 8, rem = zb & 255;
        const float* W = (z == 0) ? Wv : (z == 1) ? Wg : Ws;
        size_t wo = (size_t)z * AA * HH;
        int a0 = (rem & 15) * 32, h0 = (rem >> 4) * 32;
        int tx = tid & 31, ty = tid >> 5;
        #pragma unroll
        for (int r = ty; r < 32; r += 8)
            t[r][tx] = W[(size_t)(h0 + r) * AA + a0 + tx];
        __syncthreads();
        #pragma unroll
        for (int r = ty; r < 32; r += 8)
            g_w[wo + (size_t)(a0 + r) * HH + h0 + tx] = __float2half(t[tx][r]);
    }
}

// ---------------------------------------------------------------------------
// Merged fp16 tensor GEMM (proven geometry): 128x128x32 tiles, 256 thr,
// 8 warps (2x4), warp tile 64x32, SROW=40-padded LDS frags, 2-stage cp.async.
// grid (4 n-tiles, 65 m-tiles): my<49 -> cv (HALF out), my<57 -> cg, else cs.
#define SROW 40
#define TILE_E (128 * SROW)    // 5120 halves = 10240 B

__global__ void __launch_bounds__(256, 2) mma_gemm_all(
        const __half* __restrict__ X, const __half* __restrict__ Wt,
        __half* __restrict__ cvh, float* __restrict__ cg, float* __restrict__ cs) {
    __shared__ __half sA[2][TILE_E];
    __shared__ __half sB[2][TILE_E];

    int tid = threadIdx.x, wid = tid >> 5, lane = tid & 31;
    int wm = wid >> 2, wn = wid & 3;
    int g = lane >> 2, tig = lane & 3;
    int my = blockIdx.y;
    int n0 = blockIdx.x * 128;

    int arow0; size_t wo; float* C; int crow0; bool halfout;
    if (my < 49)      { arow0 = my * 128;                    wo = 0;                      C = nullptr; crow0 = my * 128; halfout = true; }
    else if (my < 57) { arow0 = ROWS_ATT + (my - 49) * 128;  wo = (size_t)AA * HH;        C = cg; crow0 = (my - 49) * 128; halfout = false; }
    else              { arow0 = ROWS_ATT + ROWS_HID + (my - 57) * 128; wo = 2 * (size_t)AA * HH; C = cs; crow0 = (my - 57) * 128; halfout = false; }

    float acc[4][4][4];
    #pragma unroll
    for (int i = 0; i < 4; i++)
        #pragma unroll
        for (int j = 0; j < 4; j++)
            #pragma unroll
            for (int q = 0; q < 4; q++) acc[i][j][q] = 0.0f;

    int lr = tid >> 2, lc = (tid & 3) * 8;   // row 0..63, col 0/8/16/24
    uint32_t sbA = smem_u32(sA), sbB = smem_u32(sB);

    auto load_stage = [&](int s, int k0) {
        uint32_t soff  = (uint32_t)(lr * SROW + lc) * 2;
        uint32_t soff2 = (uint32_t)((lr + 64) * SROW + lc) * 2;
        uint32_t bA = sbA + (uint32_t)s * (TILE_E * 2);
        uint32_t bB = sbB + (uint32_t)s * (TILE_E * 2);
        cp16(bA + soff,  X + (size_t)(arow0 + lr) * GK + k0 + lc);
        cp16(bA + soff2, X + (size_t)(arow0 + lr + 64) * GK + k0 + lc);
        cp16(bB + soff,  Wt + wo + (size_t)(n0 + lr) * HH + k0 + lc);
        cp16(bB + soff2, Wt + wo + (size_t)(n0 + lr + 64) * HH + k0 + lc);
    };

    load_stage(0, 0);
    CP_COMMIT();

    const int NIT = GK / 32;   // 16
    for (int it = 0; it < NIT; it++) {
        if (it + 1 < NIT) { load_stage((it + 1) & 1, (it + 1) * 32); CP_COMMIT(); CP_WAIT1(); }
        else              { CP_WAIT0(); }
        __syncthreads();

        const __half* A = sA[it & 1];
        const __half* B = sB[it & 1];

        #pragma unroll
        for (int ks = 0; ks < 2; ks++) {
            int c0 = ks * 16 + 2 * tig;
            uint32_t aF[4][4], bF[4][2];
            #pragma unroll
            for (int mf = 0; mf < 4; mf++) {
                int mr = wm * 64 + mf * 16;
                aF[mf][0] = *(const uint32_t*)&A[(mr + g) * SROW + c0];
                aF[mf][1] = *(const uint32_t*)&A[(mr + g + 8) * SROW + c0];
                aF[mf][2] = *(const uint32_t*)&A[(mr + g) * SROW + c0 + 8];
                aF[mf][3] = *(const uint32_t*)&A[(mr + g + 8) * SROW + c0 + 8];
            }
            #pragma unroll
            for (int nf = 0; nf < 4; nf++) {
                int nr = wn * 32 + nf * 8;
                bF[nf][0] = *(const uint32_t*)&B[(nr + g) * SROW + c0];
                bF[nf][1] = *(const uint32_t*)&B[(nr + g) * SROW + c0 + 8];
            }
            #pragma unroll
            for (int mf = 0; mf < 4; mf++)
                #pragma unroll
                for (int nf = 0; nf < 4; nf++) hmma(acc[mf][nf], aF[mf], bF[nf]);
        }
        __syncthreads();
    }

    if (halfout) {
        __half2* Ch = (__half2*)cvh;
        #pragma unroll
        for (int mf = 0; mf < 4; mf++) {
            int row = crow0 + wm * 64 + mf * 16 + g;
            #pragma unroll
            for (int nf = 0; nf < 4; nf++) {
                int colp = (n0 + wn * 32 + nf * 8 + 2 * tig) >> 1;   // half2 index
                Ch[(size_t)row * 256 + colp]       = __floats2half2_rn(acc[mf][nf][0], acc[mf][nf][1]);
                Ch[(size_t)(row + 8) * 256 + colp] = __floats2half2_rn(acc[mf][nf][2], acc[mf][nf][3]);
            }
        }
    } else {
        #pragma unroll
        for (int mf = 0; mf < 4; mf++) {
            int row = crow0 + wm * 64 + mf * 16 + g;
            #pragma unroll
            for (int nf = 0; nf < 4; nf++) {
                int col = n0 + wn * 32 + nf * 8 + 2 * tig;
                *(float2*)&C[(size_t)row * AA + col] = make_float2(acc[mf][nf][0], acc[mf][nf][1]);
                *(float2*)&C[(size_t)(row + 8) * AA + col] = make_float2(acc[mf][nf][2], acc[mf][nf][3]);
            }
        }
    }
}

// ---------------------------------------------------------------------------
// zfused v3: f16x2 tanh. grid (14, 4, 32), 256 thr; warp = one t row.
#define KT 14
#define KTILES (KK / KT)   // 14

__global__ void __launch_bounds__(256) zfused_kernel(const float* __restrict__ wh,
                                                     float* __restrict__ zout) {
    __shared__ __half2 s_cv[KT * 256];   // 14336 B

    int kt = blockIdx.x, tg = blockIdx.y, b = blockIdx.z;
    int tid = threadIdx.x, wid = tid >> 5, lane = tid & 31;
    int t = tg * 8 + wid;
    int row = b * TT + t;

    const uint4* cvp = (const uint4*)(g_cvh + ((size_t)b * KK + kt * KT) * AA);
    for (int i = tid; i < 896; i += 256)
        ((uint4*)s_cv)[i] = cvp[i];
    __syncthreads();

    __half2 cgh[8];
    float2 whr[8];
    const float* cgp = g_cg + (size_t)row * AA;
    #pragma unroll
    for (int j = 0; j < 8; j++) {
        float2 c = *(const float2*)&cgp[2 * (lane + 32 * j)];
        cgh[j] = __floats2half2_rn(c.x, c.y);
        whr[j] = *(const float2*)&wh[2 * (lane + 32 * j)];
    }

    #pragma unroll
    for (int kk = 0; kk < KT; kk++) {
        const __half2* cvk = s_cv + kk * 256;
        float a0 = 0.0f, a1 = 0.0f;
        #pragma unroll
        for (int j = 0; j < 8; j += 2) {
            __half2 s0 = __hadd2(cvk[lane + 32 * j],       cgh[j]);
            __half2 s1 = __hadd2(cvk[lane + 32 * (j + 1)], cgh[j + 1]);
            float2 f0 = __half22float2(tanh_h2(s0));
            float2 f1 = __half22float2(tanh_h2(s1));
            a0 = fmaf(whr[j].x,     f0.x, a0);
            a1 = fmaf(whr[j].y,     f0.y, a1);
            a0 = fmaf(whr[j + 1].x, f1.x, a0);
            a1 = fmaf(whr[j + 1].y, f1.y, a1);
        }
        float acc = warp_sum(a0 + a1);
        if (lane == 0)
            zout[(size_t)row * KK + kt * KT + kk] = acc;
    }
}

// ---------------------------------------------------------------------------
// FUSED softmax (+z_ext) + c_t blend, v2: grid (32 b, 8 tg) = 256 blocks,
// 4 t-rows per block. Phase 1 on warps 0-3 (warp = row). Phase 2: all 8 warps,
// k-loop unrolled x4 with batched loads (MLP=4).
__global__ void __launch_bounds__(256) softmax_ct_kernel(
        const float* __restrict__ af, const float* __restrict__ sent,
        const float* __restrict__ wh,
        float* __restrict__ alpha, float* __restrict__ beta,
        float* __restrict__ chat) {
    __shared__ float s_alpha[4][KK];
    __shared__ float s_beta[4];
    const float L2E = 1.4426950408889634f;

    int b = blockIdx.x, tg = blockIdx.y;
    int tid = threadIdx.x, wid = tid >> 5, lane = tid & 31;
    int trow0 = b * TT + tg * 4;

    // ---- Phase 1: softmax + zext + beta, warps 0-3, warp = one row ----
    if (wid < 4) {
        int row = trow0 + wid;
        float* zr = alpha + (size_t)row * KK;

        float ze;
        {
            const float* cs = g_cs + (size_t)row * AA;
            const float* cg = g_cg + (size_t)row * AA;
            float a0 = 0.0f;
            #pragma unroll
            for (int j = 0; j < 4; j++) {
                int i4 = (j * 32 + lane) * 4;
                float4 c1 = *(const float4*)&cs[i4];
                float4 c2 = *(const float4*)&cg[i4];
                float4 w4 = *(const float4*)&wh[i4];
                a0 = fmaf(w4.x, tanh_mufu(c1.x + c2.x), a0);
                a0 = fmaf(w4.y, tanh_mufu(c1.y + c2.y), a0);
                a0 = fmaf(w4.z, tanh_mufu(c1.z + c2.z), a0);
                a0 = fmaf(w4.w, tanh_mufu(c1.w + c2.w), a0);
            }
            ze = warp_sum(a0);
        }

        float v[7];
        float m = -INFINITY;
        #pragma unroll
        for (int j = 0; j < 7; j++) {
            int k = lane + 32 * j;
            v[j] = (k < KK) ? zr[k] : -INFINITY;
            m = fmaxf(m, v[j]);
        }
        #pragma unroll
        for (int o = 16; o; o >>= 1) m = fmaxf(m, __shfl_xor_sync(0xffffffffu, m, o));

        float s = 0.0f;
        #pragma unroll
        for (int j = 0; j < 7; j++) {
            float e = exp2f((v[j] - m) * L2E);
            v[j] = e;
            s += e;
        }
        s = warp_sum(s);

        float inv = __fdividef(1.0f, s);
        #pragma unroll
        for (int j = 0; j < 7; j++) {
            int k = lane + 32 * j;
            if (k < KK) {
                float a = v[j] * inv;
                zr[k] = a;
                s_alpha[wid][k] = a;
            }
        }

        if (lane == 0) {
            float m2 = fmaxf(m, ze);
            float ee = exp2f((ze - m2) * L2E);
            float s2 = s * exp2f((m - m2) * L2E) + ee;
            float be = __fdividef(ee, s2);
            beta[row] = be;
            s_beta[wid] = be;
        }
    }
    __syncthreads();

    // ---- Phase 2: c_hat = beta*sent + (1-beta)*sum_k alpha*af ----
    float acc[4][2];
    #pragma unroll
    for (int t = 0; t < 4; t++) { acc[t][0] = 0.0f; acc[t][1] = 0.0f; }

    const float* afb = af + (size_t)b * KK * HH;
    int h2 = tid * 2;
    #pragma unroll 2
    for (int k0 = 0; k0 < KK; k0 += 4) {
        float2 v0 = *(const float2*)(afb + (size_t)(k0 + 0) * HH + h2);
        float2 v1 = *(const float2*)(afb + (size_t)(k0 + 1) * HH + h2);
        float2 v2 = *(const float2*)(afb + (size_t)(k0 + 2) * HH + h2);
        float2 v3 = *(const float2*)(afb + (size_t)(k0 + 3) * HH + h2);
        #pragma unroll
        for (int t = 0; t < 4; t++) {
            float a0 = s_alpha[t][k0 + 0];
            float a1 = s_alpha[t][k0 + 1];
            float a2 = s_alpha[t][k0 + 2];
            float a3 = s_alpha[t][k0 + 3];
            acc[t][0] = fmaf(a0, v0.x, acc[t][0]);
            acc[t][1] = fmaf(a0, v0.y, acc[t][1]);
            acc[t][0] = fmaf(a1, v1.x, acc[t][0]);
            acc[t][1] = fmaf(a1, v1.y, acc[t][1]);
            acc[t][0] = fmaf(a2, v2.x, acc[t][0]);
            acc[t][1] = fmaf(a2, v2.y, acc[t][1]);
            acc[t][0] = fmaf(a3, v3.x, acc[t][0]);
            acc[t][1] = fmaf(a3, v3.y, acc[t][1]);
        }
    }

    #pragma unroll
    for (int t = 0; t < 4; t++) {
        float be = s_beta[t];
        float om = 1.0f - be;
        size_t row = (size_t)(trow0 + t);
        float2 sv = *(const float2*)(sent + row * HH + h2);
        float2 o;
        o.x = be * sv.x + om * acc[t][0];
        o.y = be * sv.y + om * acc[t][1];
        *(float2*)(chat + row * HH + h2) = o;
    }
}

// ---------------------------------------------------------------------------
extern "C" void kernel_launch(void* const* d_in, const int* in_sizes, int n_in,
                              void* d_out, int out_size) {
    const float* att  = (const float*)d_in[0];
    const float* hid  = (const float*)d_in[1];
    const float* sent = (const float*)d_in[2];
    const float* Wv   = (const float*)d_in[3];
    const float* Wg   = (const float*)d_in[4];
    const float* Ws   = (const float*)d_in[5];
    const float* wh   = (const float*)d_in[6];

    float* out   = (float*)d_out;
    float* chat  = out;                               // 524288
    float* alpha = out + (size_t)BB * TT * HH;        // 200704 (z_t staged here)
    float* beta  = alpha + (size_t)BB * TT * KK;      // 1024

    __half *x, *w, *cvh;
    float *cg, *cs;
    cudaGetSymbolAddress((void**)&x,   g_x);
    cudaGetSymbolAddress((void**)&w,   g_w);
    cudaGetSymbolAddress((void**)&cvh, g_cvh);
    cudaGetSymbolAddress((void**)&cg,  g_cg);
    cudaGetSymbolAddress((void**)&cs,  g_cs);

    // 1. prep: cast activations + transpose/cast weights (one launch)
    prep_kernel<<<NSPLIT + 768, 256>>>(att, hid, sent, Wv, Wg, Ws);
    // 2. all three GEMMs (fp16, cv -> half2 output)
    mma_gemm_all<<<dim3(4, 65), 256>>>(x, w, cvh, cg, cs);
    // 3. fused z_t (f16x2 tanh)
    zfused_kernel<<<dim3(KTILES, 4, 32), 256>>>(wh, alpha);
    // 4. fused softmax + z_ext + beta + blend (256 blocks, MLP-4 blend)
    softmax_ct_kernel<<<dim3(32, 8), 256>>>(att, sent, wh, alpha, beta, chat);
}